// round 13
// baseline (speedup 1.0000x reference)
#include <cuda_runtime.h>
#include <math.h>

#define HW 56
#define CDIM 128
#define WS 7
#define NTOK 49
#define NWIN_TOT 4096
#define NPIX 200704           // 64*56*56

typedef unsigned long long u64_t;

// ---------------- device scratch ----------------
__device__ float g_qkv[(size_t)NPIX * 384];
__device__ float g_o[(size_t)NPIX * 128];
__device__ float g_x1[(size_t)NPIX * 128];
__device__ float g_h[(size_t)NPIX * 512];
__device__ float g_bias16[13 * 13 * 4];
__device__ float g_scale[4];
__device__ float g_qkvbias[384];

// ---------------- helpers ----------------
__device__ __forceinline__ float2 ffma2(float2 a, float2 b, float2 c) {
    u64_t au = *reinterpret_cast<u64_t*>(&a);
    u64_t bu = *reinterpret_cast<u64_t*>(&b);
    u64_t cu = *reinterpret_cast<u64_t*>(&c);
    u64_t du;
    asm("fma.rn.f32x2 %0, %1, %2, %3;" : "=l"(du) : "l"(au), "l"(bu), "l"(cu));
    return *reinterpret_cast<float2*>(&du);
}

__device__ __forceinline__ void cp_async16(void* smem_dst, const void* gmem_src) {
    unsigned sa = (unsigned)__cvta_generic_to_shared(smem_dst);
    asm volatile("cp.async.cg.shared.global [%0], [%1], 16;" :: "r"(sa), "l"(gmem_src));
}
__device__ __forceinline__ void cp_async_commit() {
    asm volatile("cp.async.commit_group;");
}
__device__ __forceinline__ void cp_async_wait_all() {
    asm volatile("cp.async.wait_group 0;");
}

__device__ __forceinline__ unsigned tf32_of(float f) {
    unsigned u;
    asm("cvt.rna.tf32.f32 %0, %1;" : "=r"(u) : "f"(f));
    return u;
}

__device__ __forceinline__ void mma_tf32(float d[4], const unsigned a[4],
                                         const unsigned b[2], const float c[4]) {
    asm("mma.sync.aligned.m16n8k8.row.col.f32.tf32.tf32.f32 "
        "{%0,%1,%2,%3}, {%4,%5,%6,%7}, {%8,%9}, {%10,%11,%12,%13};"
        : "=f"(d[0]), "=f"(d[1]), "=f"(d[2]), "=f"(d[3])
        : "r"(a[0]), "r"(a[1]), "r"(a[2]), "r"(a[3]),
          "r"(b[0]), "r"(b[1]),
          "f"(c[0]), "f"(c[1]), "f"(c[2]), "f"(c[3]));
}

__device__ __forceinline__ float gelu_exact(float z) {
    return 0.5f * z * (1.0f + erff(z * 0.7071067811865475f));
}

__device__ __forceinline__ size_t scatter_off(int r) {
    unsigned r_ = (unsigned)r;
    unsigned win = r_ / 49u, p = r_ - win * 49u;
    unsigned b = win >> 6, wloc = win & 63u, wr = wloc >> 3, wc = wloc & 7u;
    unsigned ii = p / 7u, jj = p - ii * 7u;
    unsigned sr = wr * 7 + ii + 3; if (sr >= 56) sr -= 56;
    unsigned sc = wc * 7 + jj + 3; if (sc >= 56) sc -= 56;
    return ((size_t)((b * 56 + sr) * 56 + sc)) * 128;
}

__device__ __forceinline__ void sts_tf32x4(float* dst, float4 a) {
    uint4 u;
    u.x = tf32_of(a.x); u.y = tf32_of(a.y); u.z = tf32_of(a.z); u.w = tf32_of(a.w);
    *reinterpret_cast<uint4*>(dst) = u;
}

// ---------------- K1: prep ----------------
__device__ __forceinline__ float rpb_f(float v) {
    float sv = v * (2.0f / 9.0f);
    float s = (sv > 0.f) ? 1.f : ((sv < 0.f) ? -1.f : 0.f);
    return s * log1pf(fabsf(sv)) * (1.0f / 2.0794415416798357f);
}

__global__ void k_prep(const float* __restrict__ logit_scale,
                       const float* __restrict__ rpe_w1,
                       const float* __restrict__ rpe_b1,
                       const float* __restrict__ rpe_w2,
                       const float* __restrict__ q_bias,
                       const float* __restrict__ v_bias) {
    int bid = blockIdx.x, t = threadIdx.x;
    if (bid == 169) {
        if (t < 4) g_scale[t] = expf(fminf(logit_scale[t], logf(100.0f)));
        for (int c = t; c < 384; c += 128)
            g_qkvbias[c] = (c < 128) ? q_bias[c] : (c >= 256 ? v_bias[c - 256] : 0.f);
        return;
    }
    int dy = bid / 13 - 6, dx = bid % 13 - 6;
    float t0 = rpb_f((float)dy), t1 = rpb_f((float)dx);
    float a0 = 0, a1 = 0, a2 = 0, a3 = 0;
    for (int k = t; k < 512; k += 128) {
        float hsum = fmaf(t0, rpe_w1[k], fmaf(t1, rpe_w1[512 + k], rpe_b1[k]));
        if (hsum > 0.f) {
            const float* w2r = rpe_w2 + k * 4;
            a0 = fmaf(hsum, w2r[0], a0);
            a1 = fmaf(hsum, w2r[1], a1);
            a2 = fmaf(hsum, w2r[2], a2);
            a3 = fmaf(hsum, w2r[3], a3);
        }
    }
    #pragma unroll
    for (int o = 16; o; o >>= 1) {
        a0 += __shfl_xor_sync(0xffffffffu, a0, o);
        a1 += __shfl_xor_sync(0xffffffffu, a1, o);
        a2 += __shfl_xor_sync(0xffffffffu, a2, o);
        a3 += __shfl_xor_sync(0xffffffffu, a3, o);
    }
    __shared__ float red[4][4];
    int w = t >> 5;
    if ((t & 31) == 0) { red[w][0] = a0; red[w][1] = a1; red[w][2] = a2; red[w][3] = a3; }
    __syncthreads();
    if (t < 4) {
        float s = red[0][t] + red[1][t] + red[2][t] + red[3][t];
        g_bias16[bid * 4 + t] = 16.f / (1.f + expf(-s));
    }
}

// =================================================================
// A-resident tf32 GEMM (K=128, N>128): qkv / fc1
// 512 threads, 16 warps (4m x 4n), warp tile 32x32
// EPI: 0 = bias ; 2 = bias + gelu
// =================================================================
#define ARS 132
#define BRS 136
#define SM_ARES (128*ARS*4 + 2*16*BRS*4)

template<int N, int EPI>
__global__ void __launch_bounds__(512, 2) k_gemm_ares(
    const float* __restrict__ A, const float* __restrict__ Bm,
    const float* __restrict__ bias, float* __restrict__ out)
{
    extern __shared__ float smdyn[];
    float* Asm = smdyn;
    float* Bs0 = Asm + 128 * ARS;
    float* Bs1 = Bs0 + 16 * BRS;

    int t = threadIdx.x;
    int lane = t & 31, warp = t >> 5;
    int wm = warp >> 2, wn = warp & 3;
    int gid = lane >> 2, tig = lane & 3;
    int bm = blockIdx.x * 128;

    // A tile: 128x128, each thread loads 32 floats (row t>>2, cols (t&3)*32..)
    {
        const float* Ap = A + (size_t)(bm + (t >> 2)) * 128 + (t & 3) * 32;
        float* as = Asm + (t >> 2) * ARS + (t & 3) * 32;
        #pragma unroll
        for (int j = 0; j < 8; ++j) cp_async16(as + j * 4, Ap + j * 4);
        cp_async_commit();
        cp_async_wait_all();
        #pragma unroll 8
        for (int i = 0; i < 32; ++i) as[i] = __uint_as_float(tf32_of(as[i]));
    }

    // B staging: each thread 1 float4 per stage
    int bk = t >> 5, bc = (t & 31) * 4;
    {
        float4 r0 = *(const float4*)(Bm + (size_t)bk * N + bc);
        sts_tf32x4(Bs0 + bk * BRS + bc, r0);
    }
    __syncthreads();

    float acc[2][4][4];
    #pragma unroll
    for (int i = 0; i < 2; ++i)
        #pragma unroll
        for (int j = 0; j < 4; ++j)
            #pragma unroll
            for (int e = 0; e < 4; ++e) acc[i][j][e] = 0.f;

    const int T = (N / 128) * 8;
    float4 r0;
    #pragma unroll 1
    for (int st = 0; st < T; ++st) {
        float* bsC = (st & 1) ? Bs1 : Bs0;
        float* bsN = (st & 1) ? Bs0 : Bs1;
        if (st + 1 < T) {
            int nt1 = (st + 1) >> 3, s1 = (st + 1) & 7;
            r0 = *(const float4*)(Bm + (size_t)(s1 * 16 + bk) * N + nt1 * 128 + bc);
        }
        int kb0 = (st & 7) * 16;
        #pragma unroll
        for (int kb = 0; kb < 16; kb += 8) {
            unsigned af[2][4];
            #pragma unroll
            for (int i = 0; i < 2; ++i) {
                const float* ab = &Asm[(wm * 32 + i * 16 + gid) * ARS + kb0 + kb + tig];
                af[i][0] = __float_as_uint(ab[0]);
                af[i][1] = __float_as_uint(ab[8 * ARS]);
                af[i][2] = __float_as_uint(ab[4]);
                af[i][3] = __float_as_uint(ab[8 * ARS + 4]);
            }
            #pragma unroll
            for (int j = 0; j < 4; ++j) {
                unsigned bf[2];
                int ncol = wn * 32 + j * 8 + gid;
                bf[0] = __float_as_uint(bsC[(kb + tig) * BRS + ncol]);
                bf[1] = __float_as_uint(bsC[(kb + tig + 4) * BRS + ncol]);
                mma_tf32(acc[0][j], af[0], bf, acc[0][j]);
                mma_tf32(acc[1][j], af[1], bf, acc[1][j]);
            }
        }

        if ((st & 7) == 7) {
            int nt = st >> 3;
            int cb = nt * 128 + wn * 32;
            #pragma unroll
            for (int i = 0; i < 2; ++i) {
                int rr0 = bm + wm * 32 + i * 16 + gid;
                #pragma unroll
                for (int j = 0; j < 4; ++j) {
                    int c = cb + j * 8 + tig * 2;
                    float2 bb = *(const float2*)(bias + c);
                    float2 v0 = make_float2(acc[i][j][0] + bb.x, acc[i][j][1] + bb.y);
                    float2 v1 = make_float2(acc[i][j][2] + bb.x, acc[i][j][3] + bb.y);
                    if (EPI == 2) {
                        v0.x = gelu_exact(v0.x); v0.y = gelu_exact(v0.y);
                        v1.x = gelu_exact(v1.x); v1.y = gelu_exact(v1.y);
                    }
                    *(float2*)(out + (size_t)rr0 * N + c) = v0;
                    *(float2*)(out + (size_t)(rr0 + 8) * N + c) = v1;
                }
            }
            if (st + 1 < T) {
                #pragma unroll
                for (int i = 0; i < 2; ++i)
                    #pragma unroll
                    for (int j = 0; j < 4; ++j)
                        #pragma unroll
                        for (int e = 0; e < 4; ++e) acc[i][j][e] = 0.f;
            }
        }
        if (st + 1 < T) {
            sts_tf32x4(bsN + bk * BRS + bc, r0);
            __syncthreads();
        }
    }
}

// =================================================================
// streaming tf32 GEMM: 512 threads, 16 warps (4m x 4n), warp tile 32x32
// 2-stage cp.async, per-use cvt.
// EPI 0 = bias ; 3 = bias+LN+residual (row order) ; 4 = bias+LN+residual (scatter)
// =================================================================
#define AS 20
#define BSo 136

template<int K, int N, int EPI>
__global__ void __launch_bounds__(512, 2) k_gemm_tc(
    const float* __restrict__ A, const float* __restrict__ Bm,
    const float* __restrict__ bias, float* __restrict__ out,
    const float* __restrict__ resid, const float* __restrict__ lng,
    const float* __restrict__ lnb)
{
    __shared__ __align__(16) float Asm[2][128 * AS];
    __shared__ __align__(16) float Bs[2][16 * BSo];
    __shared__ float ssum[128][4], ssq[128][4];
    int t = threadIdx.x;
    int lane = t & 31, warp = t >> 5;
    int wm = warp >> 2, wn = warp & 3;
    int gid = lane >> 2, tig = lane & 3;
    int bm = blockIdx.x * 128, bn = blockIdx.y * 128;

    int ar0 = t >> 2, ac0 = (t & 3) * 4;
    int bk = t >> 5, bc = (t & 31) * 4;

    const float* Ap = A + (size_t)(bm + ar0) * K + ac0;
    const float* Bp = Bm + (size_t)bk * N + bn + bc;

    cp_async16(&Asm[0][ar0 * AS + ac0], Ap);
    cp_async16(&Bs[0][bk * BSo + bc], Bp);
    cp_async_commit();
    cp_async_wait_all();
    __syncthreads();

    float acc[2][4][4];
    #pragma unroll
    for (int i = 0; i < 2; ++i)
        #pragma unroll
        for (int j = 0; j < 4; ++j)
            #pragma unroll
            for (int e = 0; e < 4; ++e) acc[i][j][e] = 0.f;

    const int S = K / 16;
    #pragma unroll 1
    for (int s = 0; s < S; ++s) {
        int buf = s & 1;
        if (s + 1 < S) {
            int nb = buf ^ 1;
            cp_async16(&Asm[nb][ar0 * AS + ac0], Ap + (s + 1) * 16);
            cp_async16(&Bs[nb][bk * BSo + bc], Bp + (size_t)(s + 1) * 16 * N);
            cp_async_commit();
        }
        #pragma unroll
        for (int kb = 0; kb < 16; kb += 8) {
            unsigned af[2][4];
            #pragma unroll
            for (int i = 0; i < 2; ++i) {
                const float* ab = &Asm[buf][(wm * 32 + i * 16 + gid) * AS + kb + tig];
                af[i][0] = tf32_of(ab[0]);
                af[i][1] = tf32_of(ab[8 * AS]);
                af[i][2] = tf32_of(ab[4]);
                af[i][3] = tf32_of(ab[8 * AS + 4]);
            }
            #pragma unroll
            for (int j = 0; j < 4; ++j) {
                unsigned bf[2];
                int ncol = wn * 32 + j * 8 + gid;
                bf[0] = tf32_of(Bs[buf][(kb + tig) * BSo + ncol]);
                bf[1] = tf32_of(Bs[buf][(kb + tig + 4) * BSo + ncol]);
                mma_tf32(acc[0][j], af[0], bf, acc[0][j]);
                mma_tf32(acc[1][j], af[1], bf, acc[1][j]);
            }
        }
        if (s + 1 < S) {
            cp_async_wait_all();
            __syncthreads();
        }
    }

    if (EPI == 0) {
        #pragma unroll
        for (int i = 0; i < 2; ++i) {
            int r0 = bm + wm * 32 + i * 16 + gid;
            #pragma unroll
            for (int j = 0; j < 4; ++j) {
                int c = bn + wn * 32 + j * 8 + tig * 2;
                float2 bb = *(const float2*)(bias + c);
                float2 v0 = make_float2(acc[i][j][0] + bb.x, acc[i][j][1] + bb.y);
                float2 v1 = make_float2(acc[i][j][2] + bb.x, acc[i][j][3] + bb.y);
                *(float2*)(out + (size_t)r0 * N + c) = v0;
                *(float2*)(out + (size_t)(r0 + 8) * N + c) = v1;
            }
        }
    } else {
        __syncthreads();
        #pragma unroll
        for (int i = 0; i < 2; ++i) {
            float ps0 = 0.f, pq0 = 0.f, ps1 = 0.f, pq1 = 0.f;
            #pragma unroll
            for (int j = 0; j < 4; ++j) {
                int c = wn * 32 + j * 8 + tig * 2;
                float2 bb = *(const float2*)(bias + c);
                acc[i][j][0] += bb.x; acc[i][j][1] += bb.y;
                acc[i][j][2] += bb.x; acc[i][j][3] += bb.y;
                ps0 += acc[i][j][0] + acc[i][j][1];
                pq0 += acc[i][j][0] * acc[i][j][0] + acc[i][j][1] * acc[i][j][1];
                ps1 += acc[i][j][2] + acc[i][j][3];
                pq1 += acc[i][j][2] * acc[i][j][2] + acc[i][j][3] * acc[i][j][3];
            }
            #pragma unroll
            for (int o = 1; o < 4; o <<= 1) {
                ps0 += __shfl_xor_sync(0xffffffffu, ps0, o);
                pq0 += __shfl_xor_sync(0xffffffffu, pq0, o);
                ps1 += __shfl_xor_sync(0xffffffffu, ps1, o);
                pq1 += __shfl_xor_sync(0xffffffffu, pq1, o);
            }
            if (tig == 0) {
                int ra = wm * 32 + i * 16 + gid;
                ssum[ra][wn] = ps0; ssq[ra][wn] = pq0;
                ssum[ra + 8][wn] = ps1; ssq[ra + 8][wn] = pq1;
            }
        }
        __syncthreads();
        #pragma unroll
        for (int i = 0; i < 2; ++i) {
            int ra = wm * 32 + i * 16 + gid;
            #pragma unroll
            for (int h = 0; h < 2; ++h) {
                int row = ra + h * 8;
                float s = ssum[row][0] + ssum[row][1] + ssum[row][2] + ssum[row][3];
                float q2 = ssq[row][0] + ssq[row][1] + ssq[row][2] + ssq[row][3];
                float m = s * (1.f / 128.f);
                float var = q2 * (1.f / 128.f) - m * m;
                float inv = rsqrtf(var + 1e-3f);
                size_t off = (EPI == 4) ? scatter_off(bm + row) : (size_t)(bm + row) * 128;
                #pragma unroll
                for (int j = 0; j < 4; ++j) {
                    int c = wn * 32 + j * 8 + tig * 2;
                    float2 gg = *(const float2*)(lng + c);
                    float2 be = *(const float2*)(lnb + c);
                    float2 xr = *(const float2*)(resid + off + c);
                    float e0 = acc[i][j][2 * h], e1 = acc[i][j][2 * h + 1];
                    float2 o2;
                    o2.x = xr.x + (e0 - m) * inv * gg.x + be.x;
                    o2.y = xr.y + (e1 - m) * inv * gg.y + be.y;
                    *(float2*)(out + off + c) = o2;
                }
            }
        }
    }
}

// ---------------- K-core: per-(window, head) attention (R12 config) ----------------
#define HQS 36

__global__ void __launch_bounds__(128) k_core(const float* __restrict__ mask) {
    __shared__ float q[NTOK * HQS];
    __shared__ float kk[NTOK * HQS];
    __shared__ float v[NTOK * 32];
    __shared__ float at[NTOK * NTOK];
    __shared__ int pix[NTOK];

    int t = threadIdx.x;
    int lane = t & 31, warp = t >> 5;
    int win = blockIdx.x, h = blockIdx.y;
    int b = win >> 6, wloc = win & 63, wr = wloc >> 3, wc = wloc & 7;

    if (t < NTOK) {
        int i = t / WS, j = t % WS;
        int sr = (wr * WS + i + 3) % HW;
        int sc = (wc * WS + j + 3) % HW;
        pix[t] = (b * HW + sr) * HW + sc;
    }
    __syncthreads();

    for (int idx = t; idx < NTOK * 16; idx += 128) {
        int p = idx >> 4, c2 = idx & 15;
        const float* base = g_qkv + (size_t)pix[p] * 384 + h * 32 + c2 * 2;
        *(float2*)(q + p * HQS + c2 * 2)  = *(const float2*)(base);
        *(float2*)(kk + p * HQS + c2 * 2) = *(const float2*)(base + 128);
        *(float2*)(v + p * 32 + c2 * 2)   = *(const float2*)(base + 256);
    }
    __syncthreads();

    if (t < 2 * NTOK) {
        float4* b4 = (float4*)((t < NTOK) ? (q + t * HQS) : (kk + (t - NTOK) * HQS));
        float s = 0.f;
        #pragma unroll
        for (int d = 0; d < 8; ++d) {
            float4 vv = b4[d];
            s += vv.x * vv.x + vv.y * vv.y + vv.z * vv.z + vv.w * vv.w;
        }
        float inv = rsqrtf(fmaxf(s, 1e-12f));
        #pragma unroll
        for (int d = 0; d < 8; ++d) {
            float4 vv = b4[d];
            vv.x *= inv; vv.y *= inv; vv.z *= inv; vv.w *= inv;
            b4[d] = vv;
        }
    }
    __syncthreads();

    float scal = g_scale[h];
    const float* mw = mask + (size_t)wloc * (NTOK * NTOK);
    for (int idx = t; idx < 625; idx += 128) {
        int tp = idx / 25, tq = idx - tp * 25;
        int p0 = tp * 2, q0 = tq * 2;
        int p1 = (p0 + 1 < NTOK) ? p0 + 1 : p0;
        int q1 = (q0 + 1 < NTOK) ? q0 + 1 : q0;
        const float4* qa = (const float4*)(q + p0 * HQS);
        const float4* qb = (const float4*)(q + p1 * HQS);
        const float4* ka = (const float4*)(kk + q0 * HQS);
        const float4* kb = (const float4*)(kk + q1 * HQS);
        float2 c00 = make_float2(0.f, 0.f), c01 = make_float2(0.f, 0.f);
        float2 c10 = make_float2(0.f, 0.f), c11 = make_float2(0.f, 0.f);
        #pragma unroll
        for (int d = 0; d < 8; ++d) {
            float4 qv0 = qa[d], qv1 = qb[d], kv0 = ka[d], kv1 = kb[d];
            float2 q0l = make_float2(qv0.x, qv0.y), q0h = make_float2(qv0.z, qv0.w);
            float2 q1l = make_float2(qv1.x, qv1.y), q1h = make_float2(qv1.z, qv1.w);
            float2 k0l = make_float2(kv0.x, kv0.y), k0h = make_float2(kv0.z, kv0.w);
            float2 k1l = make_float2(kv1.x, kv1.y), k1h = make_float2(kv1.z, kv1.w);
            c00 = ffma2(q0l, k0l, c00); c00 = ffma2(q0h, k0h, c00);
            c01 = ffma2(q0l, k1l, c01); c01 = ffma2(q0h, k1h, c01);
            c10 = ffma2(q1l, k0l, c10); c10 = ffma2(q1h, k0h, c10);
            c11 = ffma2(q1l, k1l, c11); c11 = ffma2(q1h, k1h, c11);
        }
        int py0 = p0 / WS, px0 = p0 - py0 * WS;
        int py1 = p1 / WS, px1 = p1 - py1 * WS;
        int qy0 = q0 / WS, qx0 = q0 - qy0 * WS;
        int qy1 = q1 / WS, qx1 = q1 - qy1 * WS;
        at[p0 * NTOK + q0] = fmaf(c00.x + c00.y, scal,
            g_bias16[((py0 - qy0 + 6) * 13 + px0 - qx0 + 6) * 4 + h] + mw[p0 * NTOK + q0]);
        if (q1 != q0)
            at[p0 * NTOK + q1] = fmaf(c01.x + c01.y, scal,
                g_bias16[((py0 - qy1 + 6) * 13 + px0 - qx1 + 6) * 4 + h] + mw[p0 * NTOK + q1]);
        if (p1 != p0) {
            at[p1 * NTOK + q0] = fmaf(c10.x + c10.y, scal,
                g_bias16[((py1 - qy0 + 6) * 13 + px1 - qx0 + 6) * 4 + h] + mw[p1 * NTOK + q0]);
            if (q1 != q0)
                at[p1 * NTOK + q1] = fmaf(c11.x + c11.y, scal,
                    g_bias16[((py1 - qy1 + 6) * 13 + px1 - qx1 + 6) * 4 + h] + mw[p1 * NTOK + q1]);
        }
    }
    __syncthreads();

    for (int row = warp; row < NTOK; row += 4) {
        float* r = at + row * NTOK;
        float v0 = r[lane < NTOK ? lane : 0];
        if (lane >= NTOK) v0 = -1e30f;
        float v1 = (lane + 32 < NTOK) ? r[lane + 32] : -1e30f;
        float m = fmaxf(v0, v1);
        #pragma unroll
        for (int o = 16; o; o >>= 1) m = fmaxf(m, __shfl_xor_sync(0xffffffffu, m, o));
        float e0 = (lane < NTOK) ? expf(v0 - m) : 0.f;
        float e1 = (lane + 32 < NTOK) ? expf(v1 - m) : 0.f;
        float s = e0 + e1;
        #pragma unroll
        for (int o = 16; o; o >>= 1) s += __shfl_xor_sync(0xffffffffu, s, o);
        float inv = 1.f / s;
        if (lane < NTOK) r[lane] = e0 * inv;
        if (lane + 32 < NTOK) r[lane + 32] = e1 * inv;
    }
    __syncthreads();

    const float2* v2 = (const float2*)v;
    for (int idx = t; idx < 400; idx += 128) {
        int pp = idx >> 4, cp = idx & 15;
        int p0 = pp * 2, p1 = p0 + 1;
        bool has1 = (p1 < NTOK);
        const float* ar0 = at + p0 * NTOK;
        const float* ar1 = at + (has1 ? p1 : p0) * NTOK;
        float2 acc0 = make_float2(0.f, 0.f), acc1 = make_float2(0.f, 0.f);
        #pragma unroll 7
        for (int qq = 0; qq < NTOK; ++qq) {
            float2 vv = v2[qq * 16 + cp];
            float a0 = ar0[qq], a1 = ar1[qq];
            acc0 = ffma2(make_float2(a0, a0), vv, acc0);
            acc1 = ffma2(make_float2(a1, a1), vv, acc1);
        }
        *(float2*)(g_o + ((size_t)win * NTOK + p0) * 128 + h * 32 + cp * 2) = acc0;
        if (has1)
            *(float2*)(g_o + ((size_t)win * NTOK + p1) * 128 + h * 32 + cp * 2) = acc1;
    }
}

// ---------------- launch ----------------
extern "C" void kernel_launch(void* const* d_in, const int* in_sizes, int n_in,
                              void* d_out, int out_size) {
    const float* x           = (const float*)d_in[0];
    const float* mask        = (const float*)d_in[1];
    const float* norm1_g     = (const float*)d_in[2];
    const float* norm1_b     = (const float*)d_in[3];
    const float* qkv_w       = (const float*)d_in[4];
    const float* q_bias      = (const float*)d_in[5];
    const float* v_bias      = (const float*)d_in[6];
    const float* logit_scale = (const float*)d_in[7];
    const float* rpe_w1      = (const float*)d_in[8];
    const float* rpe_b1      = (const float*)d_in[9];
    const float* rpe_w2      = (const float*)d_in[10];
    const float* proj_w      = (const float*)d_in[11];
    const float* proj_b      = (const float*)d_in[12];
    const float* norm2_g     = (const float*)d_in[13];
    const float* norm2_b     = (const float*)d_in[14];
    const float* fc1_w       = (const float*)d_in[15];
    const float* fc1_b       = (const float*)d_in[16];
    const float* fc2_w       = (const float*)d_in[17];
    const float* fc2_b       = (const float*)d_in[18];
    float* out = (float*)d_out;

    float *p_qkv, *p_o, *p_x1, *p_h, *p_qb;
    cudaGetSymbolAddress((void**)&p_qkv, g_qkv);
    cudaGetSymbolAddress((void**)&p_o,   g_o);
    cudaGetSymbolAddress((void**)&p_x1,  g_x1);
    cudaGetSymbolAddress((void**)&p_h,   g_h);
    cudaGetSymbolAddress((void**)&p_qb,  g_qkvbias);

    cudaFuncSetAttribute(k_gemm_ares<384, 0>, cudaFuncAttributeMaxDynamicSharedMemorySize, SM_ARES);
    cudaFuncSetAttribute(k_gemm_ares<512, 2>, cudaFuncAttributeMaxDynamicSharedMemorySize, SM_ARES);

    k_prep<<<170, 128>>>(logit_scale, rpe_w1, rpe_b1, rpe_w2, q_bias, v_bias);

    k_gemm_ares<384, 0><<<NPIX / 128, 512, SM_ARES>>>(x, qkv_w, p_qb, p_qkv);

    dim3 gc(NWIN_TOT, 4);
    k_core<<<gc, 128>>>(mask);

    dim3 gp(NPIX / 128, 1);
    k_gemm_tc<128, 128, 4><<<gp, 512>>>(p_o, proj_w, proj_b, p_x1,
                                        x, norm1_g, norm1_b);

    k_gemm_ares<512, 2><<<NPIX / 128, 512, SM_ARES>>>(p_x1, fc1_w, fc1_b, p_h);

    dim3 g2(NPIX / 128, 1);
    k_gemm_tc<512, 128, 3><<<g2, 512>>>(p_h, fc2_w, fc2_b, out,
                                        p_x1, norm2_g, norm2_b);
}

// round 14
// speedup vs baseline: 1.0559x; 1.0559x over previous
#include <cuda_runtime.h>
#include <math.h>

#define HW 56
#define CDIM 128
#define WS 7
#define NTOK 49
#define NWIN_TOT 4096
#define NPIX 200704           // 64*56*56

typedef unsigned long long u64_t;

// ---------------- device scratch ----------------
__device__ float g_qkv[(size_t)NPIX * 384];
__device__ float g_o[(size_t)NPIX * 128];
__device__ float g_x1[(size_t)NPIX * 128];
__device__ float g_h[(size_t)NPIX * 512];
__device__ float g_bias16[13 * 13 * 4];
__device__ float g_scale[4];
__device__ float g_qkvbias[384];

// ---------------- helpers ----------------
__device__ __forceinline__ float2 ffma2(float2 a, float2 b, float2 c) {
    u64_t au = *reinterpret_cast<u64_t*>(&a);
    u64_t bu = *reinterpret_cast<u64_t*>(&b);
    u64_t cu = *reinterpret_cast<u64_t*>(&c);
    u64_t du;
    asm("fma.rn.f32x2 %0, %1, %2, %3;" : "=l"(du) : "l"(au), "l"(bu), "l"(cu));
    return *reinterpret_cast<float2*>(&du);
}

__device__ __forceinline__ void cp_async16(void* smem_dst, const void* gmem_src) {
    unsigned sa = (unsigned)__cvta_generic_to_shared(smem_dst);
    asm volatile("cp.async.cg.shared.global [%0], [%1], 16;" :: "r"(sa), "l"(gmem_src));
}
__device__ __forceinline__ void cp_async_commit() {
    asm volatile("cp.async.commit_group;");
}
__device__ __forceinline__ void cp_async_wait_all() {
    asm volatile("cp.async.wait_group 0;");
}

__device__ __forceinline__ unsigned tf32_of(float f) {
    unsigned u;
    asm("cvt.rna.tf32.f32 %0, %1;" : "=r"(u) : "f"(f));
    return u;
}

__device__ __forceinline__ void mma_tf32(float d[4], const unsigned a[4],
                                         const unsigned b[2], const float c[4]) {
    asm("mma.sync.aligned.m16n8k8.row.col.f32.tf32.tf32.f32 "
        "{%0,%1,%2,%3}, {%4,%5,%6,%7}, {%8,%9}, {%10,%11,%12,%13};"
        : "=f"(d[0]), "=f"(d[1]), "=f"(d[2]), "=f"(d[3])
        : "r"(a[0]), "r"(a[1]), "r"(a[2]), "r"(a[3]),
          "r"(b[0]), "r"(b[1]),
          "f"(c[0]), "f"(c[1]), "f"(c[2]), "f"(c[3]));
}

__device__ __forceinline__ float gelu_exact(float z) {
    return 0.5f * z * (1.0f + erff(z * 0.7071067811865475f));
}

__device__ __forceinline__ size_t scatter_off(int r) {
    unsigned r_ = (unsigned)r;
    unsigned win = r_ / 49u, p = r_ - win * 49u;
    unsigned b = win >> 6, wloc = win & 63u, wr = wloc >> 3, wc = wloc & 7u;
    unsigned ii = p / 7u, jj = p - ii * 7u;
    unsigned sr = wr * 7 + ii + 3; if (sr >= 56) sr -= 56;
    unsigned sc = wc * 7 + jj + 3; if (sc >= 56) sc -= 56;
    return ((size_t)((b * 56 + sr) * 56 + sc)) * 128;
}

// store float4 as tf32 bits (STS.128)
__device__ __forceinline__ void sts_tf32x4(float* dst, float4 a) {
    uint4 u;
    u.x = tf32_of(a.x); u.y = tf32_of(a.y); u.z = tf32_of(a.z); u.w = tf32_of(a.w);
    *reinterpret_cast<uint4*>(dst) = u;
}
__device__ __forceinline__ void sts_tf32x8(float* dst, float4 a, float4 b) {
    sts_tf32x4(dst, a);
    sts_tf32x4(dst + 4, b);
}

// ---------------- K1: prep ----------------
__device__ __forceinline__ float rpb_f(float v) {
    float sv = v * (2.0f / 9.0f);
    float s = (sv > 0.f) ? 1.f : ((sv < 0.f) ? -1.f : 0.f);
    return s * log1pf(fabsf(sv)) * (1.0f / 2.0794415416798357f);
}

__global__ void k_prep(const float* __restrict__ logit_scale,
                       const float* __restrict__ rpe_w1,
                       const float* __restrict__ rpe_b1,
                       const float* __restrict__ rpe_w2,
                       const float* __restrict__ q_bias,
                       const float* __restrict__ v_bias) {
    int bid = blockIdx.x, t = threadIdx.x;
    if (bid == 169) {
        if (t < 4) g_scale[t] = expf(fminf(logit_scale[t], logf(100.0f)));
        for (int c = t; c < 384; c += 128)
            g_qkvbias[c] = (c < 128) ? q_bias[c] : (c >= 256 ? v_bias[c - 256] : 0.f);
        return;
    }
    int dy = bid / 13 - 6, dx = bid % 13 - 6;
    float t0 = rpb_f((float)dy), t1 = rpb_f((float)dx);
    float a0 = 0, a1 = 0, a2 = 0, a3 = 0;
    for (int k = t; k < 512; k += 128) {
        float hsum = fmaf(t0, rpe_w1[k], fmaf(t1, rpe_w1[512 + k], rpe_b1[k]));
        if (hsum > 0.f) {
            const float* w2r = rpe_w2 + k * 4;
            a0 = fmaf(hsum, w2r[0], a0);
            a1 = fmaf(hsum, w2r[1], a1);
            a2 = fmaf(hsum, w2r[2], a2);
            a3 = fmaf(hsum, w2r[3], a3);
        }
    }
    #pragma unroll
    for (int o = 16; o; o >>= 1) {
        a0 += __shfl_xor_sync(0xffffffffu, a0, o);
        a1 += __shfl_xor_sync(0xffffffffu, a1, o);
        a2 += __shfl_xor_sync(0xffffffffu, a2, o);
        a3 += __shfl_xor_sync(0xffffffffu, a3, o);
    }
    __shared__ float red[4][4];
    int w = t >> 5;
    if ((t & 31) == 0) { red[w][0] = a0; red[w][1] = a1; red[w][2] = a2; red[w][3] = a3; }
    __syncthreads();
    if (t < 4) {
        float s = red[0][t] + red[1][t] + red[2][t] + red[3][t];
        g_bias16[bid * 4 + t] = 16.f / (1.f + expf(-s));
    }
}

// =================================================================
// A-resident tf32 GEMM (K=128, N>128): qkv / fc1   (R12/R8 config)
// 256 thr, 8 warps (4m x 2n), warp tile 32x64
// EPI: 0 = bias ; 2 = bias + gelu
// =================================================================
#define ARS 132
#define BRS 136
#define SM_ARES (128*ARS*4 + 2*16*BRS*4)

template<int N, int EPI>
__global__ void __launch_bounds__(256, 2) k_gemm_ares(
    const float* __restrict__ A, const float* __restrict__ Bm,
    const float* __restrict__ bias, float* __restrict__ out)
{
    extern __shared__ float smdyn[];
    float* Asm = smdyn;
    float* Bs0 = Asm + 128 * ARS;
    float* Bs1 = Bs0 + 16 * BRS;

    int t = threadIdx.x;
    int lane = t & 31, warp = t >> 5;
    int wm = warp >> 1, wn = warp & 1;
    int gid = lane >> 2, tig = lane & 3;
    int bm = blockIdx.x * 128;

    {
        const float* Ap = A + (size_t)(bm + (t >> 1)) * 128 + (t & 1) * 64;
        float* as = Asm + (t >> 1) * ARS + (t & 1) * 64;
        #pragma unroll
        for (int j = 0; j < 16; ++j) cp_async16(as + j * 4, Ap + j * 4);
        cp_async_commit();
        cp_async_wait_all();
        #pragma unroll 8
        for (int i = 0; i < 64; ++i) as[i] = __uint_as_float(tf32_of(as[i]));
    }

    int bk = t >> 4, bc = (t & 15) * 8;
    {
        const float* Bp = Bm + (size_t)bk * N + bc;
        float4 r0 = *(const float4*)Bp;
        float4 r1 = *(const float4*)(Bp + 4);
        sts_tf32x8(Bs0 + bk * BRS + bc, r0, r1);
    }
    __syncthreads();

    float acc[2][8][4];
    #pragma unroll
    for (int i = 0; i < 2; ++i)
        #pragma unroll
        for (int j = 0; j < 8; ++j)
            #pragma unroll
            for (int e = 0; e < 4; ++e) acc[i][j][e] = 0.f;

    const int T = (N / 128) * 8;
    float4 r0, r1;
    #pragma unroll 1
    for (int st = 0; st < T; ++st) {
        float* bsC = (st & 1) ? Bs1 : Bs0;
        float* bsN = (st & 1) ? Bs0 : Bs1;
        if (st + 1 < T) {
            int nt1 = (st + 1) >> 3, s1 = (st + 1) & 7;
            const float* Bp = Bm + (size_t)(s1 * 16 + bk) * N + nt1 * 128 + bc;
            r0 = *(const float4*)Bp;
            r1 = *(const float4*)(Bp + 4);
        }
        int kb0 = (st & 7) * 16;
        #pragma unroll
        for (int kb = 0; kb < 16; kb += 8) {
            unsigned af[2][4];
            #pragma unroll
            for (int i = 0; i < 2; ++i) {
                const float* ab = &Asm[(wm * 32 + i * 16 + gid) * ARS + kb0 + kb + tig];
                af[i][0] = __float_as_uint(ab[0]);
                af[i][1] = __float_as_uint(ab[8 * ARS]);
                af[i][2] = __float_as_uint(ab[4]);
                af[i][3] = __float_as_uint(ab[8 * ARS + 4]);
            }
            #pragma unroll
            for (int j = 0; j < 8; ++j) {
                unsigned bf[2];
                int ncol = wn * 64 + j * 8 + gid;
                bf[0] = __float_as_uint(bsC[(kb + tig) * BRS + ncol]);
                bf[1] = __float_as_uint(bsC[(kb + tig + 4) * BRS + ncol]);
                mma_tf32(acc[0][j], af[0], bf, acc[0][j]);
                mma_tf32(acc[1][j], af[1], bf, acc[1][j]);
            }
        }

        if ((st & 7) == 7) {
            int nt = st >> 3;
            int cb = nt * 128 + wn * 64;
            #pragma unroll
            for (int i = 0; i < 2; ++i) {
                int rr0 = bm + wm * 32 + i * 16 + gid;
                #pragma unroll
                for (int j = 0; j < 8; ++j) {
                    int c = cb + j * 8 + tig * 2;
                    float2 bb = *(const float2*)(bias + c);
                    float2 v0 = make_float2(acc[i][j][0] + bb.x, acc[i][j][1] + bb.y);
                    float2 v1 = make_float2(acc[i][j][2] + bb.x, acc[i][j][3] + bb.y);
                    if (EPI == 2) {
                        v0.x = gelu_exact(v0.x); v0.y = gelu_exact(v0.y);
                        v1.x = gelu_exact(v1.x); v1.y = gelu_exact(v1.y);
                    }
                    *(float2*)(out + (size_t)rr0 * N + c) = v0;
                    *(float2*)(out + (size_t)(rr0 + 8) * N + c) = v1;
                }
            }
            if (st + 1 < T) {
                #pragma unroll
                for (int i = 0; i < 2; ++i)
                    #pragma unroll
                    for (int j = 0; j < 8; ++j)
                        #pragma unroll
                        for (int e = 0; e < 4; ++e) acc[i][j][e] = 0.f;
            }
        }
        if (st + 1 < T) {
            sts_tf32x8(bsN + bk * BRS + bc, r0, r1);
            __syncthreads();
        }
    }
}

// =================================================================
// streaming tf32 GEMM: BM=64, BN=128, 256 thr, 8 warps (2m x 4n),
// warp tile 32x32. A: cp.async + per-use cvt; B: LDG->cvt->STS.
// EPI 3 = bias+LN+residual (row order) ; 4 = bias+LN+residual (scatter)
// =================================================================
#define AS 20
#define BSo 136

template<int K, int N, int EPI>
__global__ void __launch_bounds__(256, 3) k_gemm_tc(
    const float* __restrict__ A, const float* __restrict__ Bm,
    const float* __restrict__ bias, float* __restrict__ out,
    const float* __restrict__ resid, const float* __restrict__ lng,
    const float* __restrict__ lnb)
{
    __shared__ __align__(16) float Asm[2][64 * AS];
    __shared__ __align__(16) float Bs[2][16 * BSo];
    __shared__ float ssum[64][4], ssq[64][4];
    int t = threadIdx.x;
    int lane = t & 31, warp = t >> 5;
    int wm = warp >> 2, wn = warp & 3;
    int gid = lane >> 2, tig = lane & 3;
    int bm = blockIdx.x * 64;

    int ar0 = t >> 2, ac0 = (t & 3) * 4;
    int bk = t >> 4, bc = (t & 15) * 8;

    const float* Ap = A + (size_t)(bm + ar0) * K + ac0;
    const float* Bp = Bm + (size_t)bk * N + bc;

    // stage 0
    cp_async16(&Asm[0][ar0 * AS + ac0], Ap);
    cp_async_commit();
    {
        float4 b0 = *(const float4*)Bp;
        float4 b1 = *(const float4*)(Bp + 4);
        sts_tf32x8(&Bs[0][bk * BSo + bc], b0, b1);
    }
    cp_async_wait_all();
    __syncthreads();

    float acc[2][4][4];
    #pragma unroll
    for (int i = 0; i < 2; ++i)
        #pragma unroll
        for (int j = 0; j < 4; ++j)
            #pragma unroll
            for (int e = 0; e < 4; ++e) acc[i][j][e] = 0.f;

    const int S = K / 16;
    float4 rb0, rb1;
    #pragma unroll 1
    for (int s = 0; s < S; ++s) {
        int buf = s & 1;
        if (s + 1 < S) {
            int nb = buf ^ 1;
            cp_async16(&Asm[nb][ar0 * AS + ac0], Ap + (s + 1) * 16);
            cp_async_commit();
            const float* b2 = Bp + (size_t)(s + 1) * 16 * N;
            rb0 = *(const float4*)b2;
            rb1 = *(const float4*)(b2 + 4);
        }
        #pragma unroll
        for (int kb = 0; kb < 16; kb += 8) {
            unsigned af[2][4];
            #pragma unroll
            for (int i = 0; i < 2; ++i) {
                const float* ab = &Asm[buf][(wm * 32 + i * 16 + gid) * AS + kb + tig];
                af[i][0] = tf32_of(ab[0]);
                af[i][1] = tf32_of(ab[8 * AS]);
                af[i][2] = tf32_of(ab[4]);
                af[i][3] = tf32_of(ab[8 * AS + 4]);
            }
            #pragma unroll
            for (int j = 0; j < 4; ++j) {
                unsigned bf[2];
                int ncol = wn * 32 + j * 8 + gid;
                bf[0] = __float_as_uint(Bs[buf][(kb + tig) * BSo + ncol]);
                bf[1] = __float_as_uint(Bs[buf][(kb + tig + 4) * BSo + ncol]);
                mma_tf32(acc[0][j], af[0], bf, acc[0][j]);
                mma_tf32(acc[1][j], af[1], bf, acc[1][j]);
            }
        }
        if (s + 1 < S) {
            int nb = buf ^ 1;
            sts_tf32x8(&Bs[nb][bk * BSo + bc], rb0, rb1);
            cp_async_wait_all();
            __syncthreads();
        }
    }

    // epilogue: bias + LN + residual
    __syncthreads();
    #pragma unroll
    for (int i = 0; i < 2; ++i) {
        float ps0 = 0.f, pq0 = 0.f, ps1 = 0.f, pq1 = 0.f;
        #pragma unroll
        for (int j = 0; j < 4; ++j) {
            int c = wn * 32 + j * 8 + tig * 2;
            float2 bb = *(const float2*)(bias + c);
            acc[i][j][0] += bb.x; acc[i][j][1] += bb.y;
            acc[i][j][2] += bb.x; acc[i][j][3] += bb.y;
            ps0 += acc[i][j][0] + acc[i][j][1];
            pq0 += acc[i][j][0] * acc[i][j][0] + acc[i][j][1] * acc[i][j][1];
            ps1 += acc[i][j][2] + acc[i][j][3];
            pq1 += acc[i][j][2] * acc[i][j][2] + acc[i][j][3] * acc[i][j][3];
        }
        #pragma unroll
        for (int o = 1; o < 4; o <<= 1) {
            ps0 += __shfl_xor_sync(0xffffffffu, ps0, o);
            pq0 += __shfl_xor_sync(0xffffffffu, pq0, o);
            ps1 += __shfl_xor_sync(0xffffffffu, ps1, o);
            pq1 += __shfl_xor_sync(0xffffffffu, pq1, o);
        }
        if (tig == 0) {
            int ra = wm * 32 + i * 16 + gid;
            ssum[ra][wn] = ps0; ssq[ra][wn] = pq0;
            ssum[ra + 8][wn] = ps1; ssq[ra + 8][wn] = pq1;
        }
    }
    __syncthreads();
    #pragma unroll
    for (int i = 0; i < 2; ++i) {
        int ra = wm * 32 + i * 16 + gid;
        #pragma unroll
        for (int h = 0; h < 2; ++h) {
            int row = ra + h * 8;
            float s = ssum[row][0] + ssum[row][1] + ssum[row][2] + ssum[row][3];
            float q2 = ssq[row][0] + ssq[row][1] + ssq[row][2] + ssq[row][3];
            float m = s * (1.f / 128.f);
            float var = q2 * (1.f / 128.f) - m * m;
            float inv = rsqrtf(var + 1e-3f);
            size_t off = (EPI == 4) ? scatter_off(bm + row) : (size_t)(bm + row) * 128;
            #pragma unroll
            for (int j = 0; j < 4; ++j) {
                int c = wn * 32 + j * 8 + tig * 2;
                float2 gg = *(const float2*)(lng + c);
                float2 be = *(const float2*)(lnb + c);
                float2 xr = *(const float2*)(resid + off + c);
                float e0 = acc[i][j][2 * h], e1 = acc[i][j][2 * h + 1];
                float2 o2;
                o2.x = xr.x + (e0 - m) * inv * gg.x + be.x;
                o2.y = xr.y + (e1 - m) * inv * gg.y + be.y;
                *(float2*)(out + off + c) = o2;
            }
        }
    }
}

// ---------------- K-core: per-(window, head) attention (R12 config) ----------------
#define HQS 36

__global__ void __launch_bounds__(128) k_core(const float* __restrict__ mask) {
    __shared__ float q[NTOK * HQS];
    __shared__ float kk[NTOK * HQS];
    __shared__ float v[NTOK * 32];
    __shared__ float at[NTOK * NTOK];
    __shared__ int pix[NTOK];

    int t = threadIdx.x;
    int lane = t & 31, warp = t >> 5;
    int win = blockIdx.x, h = blockIdx.y;
    int b = win >> 6, wloc = win & 63, wr = wloc >> 3, wc = wloc & 7;

    if (t < NTOK) {
        int i = t / WS, j = t % WS;
        int sr = (wr * WS + i + 3) % HW;
        int sc = (wc * WS + j + 3) % HW;
        pix[t] = (b * HW + sr) * HW + sc;
    }
    __syncthreads();

    for (int idx = t; idx < NTOK * 16; idx += 128) {
        int p = idx >> 4, c2 = idx & 15;
        const float* base = g_qkv + (size_t)pix[p] * 384 + h * 32 + c2 * 2;
        *(float2*)(q + p * HQS + c2 * 2)  = *(const float2*)(base);
        *(float2*)(kk + p * HQS + c2 * 2) = *(const float2*)(base + 128);
        *(float2*)(v + p * 32 + c2 * 2)   = *(const float2*)(base + 256);
    }
    __syncthreads();

    if (t < 2 * NTOK) {
        float4* b4 = (float4*)((t < NTOK) ? (q + t * HQS) : (kk + (t - NTOK) * HQS));
        float s = 0.f;
        #pragma unroll
        for (int d = 0; d < 8; ++d) {
            float4 vv = b4[d];
            s += vv.x * vv.x + vv.y * vv.y + vv.z * vv.z + vv.w * vv.w;
        }
        float inv = rsqrtf(fmaxf(s, 1e-12f));
        #pragma unroll
        for (int d = 0; d < 8; ++d) {
            float4 vv = b4[d];
            vv.x *= inv; vv.y *= inv; vv.z *= inv; vv.w *= inv;
            b4[d] = vv;
        }
    }
    __syncthreads();

    float scal = g_scale[h];
    const float* mw = mask + (size_t)wloc * (NTOK * NTOK);
    for (int idx = t; idx < 625; idx += 128) {
        int tp = idx / 25, tq = idx - tp * 25;
        int p0 = tp * 2, q0 = tq * 2;
        int p1 = (p0 + 1 < NTOK) ? p0 + 1 : p0;
        int q1 = (q0 + 1 < NTOK) ? q0 + 1 : q0;
        const float4* qa = (const float4*)(q + p0 * HQS);
        const float4* qb = (const float4*)(q + p1 * HQS);
        const float4* ka = (const float4*)(kk + q0 * HQS);
        const float4* kb = (const float4*)(kk + q1 * HQS);
        float2 c00 = make_float2(0.f, 0.f), c01 = make_float2(0.f, 0.f);
        float2 c10 = make_float2(0.f, 0.f), c11 = make_float2(0.f, 0.f);
        #pragma unroll
        for (int d = 0; d < 8; ++d) {
            float4 qv0 = qa[d], qv1 = qb[d], kv0 = ka[d], kv1 = kb[d];
            float2 q0l = make_float2(qv0.x, qv0.y), q0h = make_float2(qv0.z, qv0.w);
            float2 q1l = make_float2(qv1.x, qv1.y), q1h = make_float2(qv1.z, qv1.w);
            float2 k0l = make_float2(kv0.x, kv0.y), k0h = make_float2(kv0.z, kv0.w);
            float2 k1l = make_float2(kv1.x, kv1.y), k1h = make_float2(kv1.z, kv1.w);
            c00 = ffma2(q0l, k0l, c00); c00 = ffma2(q0h, k0h, c00);
            c01 = ffma2(q0l, k1l, c01); c01 = ffma2(q0h, k1h, c01);
            c10 = ffma2(q1l, k0l, c10); c10 = ffma2(q1h, k0h, c10);
            c11 = ffma2(q1l, k1l, c11); c11 = ffma2(q1h, k1h, c11);
        }
        int py0 = p0 / WS, px0 = p0 - py0 * WS;
        int py1 = p1 / WS, px1 = p1 - py1 * WS;
        int qy0 = q0 / WS, qx0 = q0 - qy0 * WS;
        int qy1 = q1 / WS, qx1 = q1 - qy1 * WS;
        at[p0 * NTOK + q0] = fmaf(c00.x + c00.y, scal,
            g_bias16[((py0 - qy0 + 6) * 13 + px0 - qx0 + 6) * 4 + h] + mw[p0 * NTOK + q0]);
        if (q1 != q0)
            at[p0 * NTOK + q1] = fmaf(c01.x + c01.y, scal,
                g_bias16[((py0 - qy1 + 6) * 13 + px0 - qx1 + 6) * 4 + h] + mw[p0 * NTOK + q1]);
        if (p1 != p0) {
            at[p1 * NTOK + q0] = fmaf(c10.x + c10.y, scal,
                g_bias16[((py1 - qy0 + 6) * 13 + px1 - qx0 + 6) * 4 + h] + mw[p1 * NTOK + q0]);
            if (q1 != q0)
                at[p1 * NTOK + q1] = fmaf(c11.x + c11.y, scal,
                    g_bias16[((py1 - qy1 + 6) * 13 + px1 - qx1 + 6) * 4 + h] + mw[p1 * NTOK + q1]);
        }
    }
    __syncthreads();

    for (int row = warp; row < NTOK; row += 4) {
        float* r = at + row * NTOK;
        float v0 = r[lane < NTOK ? lane : 0];
        if (lane >= NTOK) v0 = -1e30f;
        float v1 = (lane + 32 < NTOK) ? r[lane + 32] : -1e30f;
        float m = fmaxf(v0, v1);
        #pragma unroll
        for (int o = 16; o; o >>= 1) m = fmaxf(m, __shfl_xor_sync(0xffffffffu, m, o));
        float e0 = (lane < NTOK) ? expf(v0 - m) : 0.f;
        float e1 = (lane + 32 < NTOK) ? expf(v1 - m) : 0.f;
        float s = e0 + e1;
        #pragma unroll
        for (int o = 16; o; o >>= 1) s += __shfl_xor_sync(0xffffffffu, s, o);
        float inv = 1.f / s;
        if (lane < NTOK) r[lane] = e0 * inv;
        if (lane + 32 < NTOK) r[lane + 32] = e1 * inv;
    }
    __syncthreads();

    const float2* v2 = (const float2*)v;
    for (int idx = t; idx < 400; idx += 128) {
        int pp = idx >> 4, cp = idx & 15;
        int p0 = pp * 2, p1 = p0 + 1;
        bool has1 = (p1 < NTOK);
        const float* ar0 = at + p0 * NTOK;
        const float* ar1 = at + (has1 ? p1 : p0) * NTOK;
        float2 acc0 = make_float2(0.f, 0.f), acc1 = make_float2(0.f, 0.f);
        #pragma unroll 7
        for (int qq = 0; qq < NTOK; ++qq) {
            float2 vv = v2[qq * 16 + cp];
            float a0 = ar0[qq], a1 = ar1[qq];
            acc0 = ffma2(make_float2(a0, a0), vv, acc0);
            acc1 = ffma2(make_float2(a1, a1), vv, acc1);
        }
        *(float2*)(g_o + ((size_t)win * NTOK + p0) * 128 + h * 32 + cp * 2) = acc0;
        if (has1)
            *(float2*)(g_o + ((size_t)win * NTOK + p1) * 128 + h * 32 + cp * 2) = acc1;
    }
}

// ---------------- launch ----------------
extern "C" void kernel_launch(void* const* d_in, const int* in_sizes, int n_in,
                              void* d_out, int out_size) {
    const float* x           = (const float*)d_in[0];
    const float* mask        = (const float*)d_in[1];
    const float* norm1_g     = (const float*)d_in[2];
    const float* norm1_b     = (const float*)d_in[3];
    const float* qkv_w       = (const float*)d_in[4];
    const float* q_bias      = (const float*)d_in[5];
    const float* v_bias      = (const float*)d_in[6];
    const float* logit_scale = (const float*)d_in[7];
    const float* rpe_w1      = (const float*)d_in[8];
    const float* rpe_b1      = (const float*)d_in[9];
    const float* rpe_w2      = (const float*)d_in[10];
    const float* proj_w      = (const float*)d_in[11];
    const float* proj_b      = (const float*)d_in[12];
    const float* norm2_g     = (const float*)d_in[13];
    const float* norm2_b     = (const float*)d_in[14];
    const float* fc1_w       = (const float*)d_in[15];
    const float* fc1_b       = (const float*)d_in[16];
    const float* fc2_w       = (const float*)d_in[17];
    const float* fc2_b       = (const float*)d_in[18];
    float* out = (float*)d_out;

    float *p_qkv, *p_o, *p_x1, *p_h, *p_qb;
    cudaGetSymbolAddress((void**)&p_qkv, g_qkv);
    cudaGetSymbolAddress((void**)&p_o,   g_o);
    cudaGetSymbolAddress((void**)&p_x1,  g_x1);
    cudaGetSymbolAddress((void**)&p_h,   g_h);
    cudaGetSymbolAddress((void**)&p_qb,  g_qkvbias);

    cudaFuncSetAttribute(k_gemm_ares<384, 0>, cudaFuncAttributeMaxDynamicSharedMemorySize, SM_ARES);
    cudaFuncSetAttribute(k_gemm_ares<512, 2>, cudaFuncAttributeMaxDynamicSharedMemorySize, SM_ARES);

    k_prep<<<170, 128>>>(logit_scale, rpe_w1, rpe_b1, rpe_w2, q_bias, v_bias);

    k_gemm_ares<384, 0><<<NPIX / 128, 256, SM_ARES>>>(x, qkv_w, p_qb, p_qkv);

    dim3 gc(NWIN_TOT, 4);
    k_core<<<gc, 128>>>(mask);

    k_gemm_tc<128, 128, 4><<<NPIX / 64, 256>>>(p_o, proj_w, proj_b, p_x1,
                                               x, norm1_g, norm1_b);

    k_gemm_ares<512, 2><<<NPIX / 128, 256, SM_ARES>>>(p_x1, fc1_w, fc1_b, p_h);

    k_gemm_tc<512, 128, 3><<<NPIX / 64, 256>>>(p_h, fc2_w, fc2_b, out,
                                               p_x1, norm2_g, norm2_b);
}

// round 15
// speedup vs baseline: 1.0724x; 1.0157x over previous
#include <cuda_runtime.h>
#include <math.h>

#define HW 56
#define CDIM 128
#define WS 7
#define NTOK 49
#define NWIN_TOT 4096
#define NPIX 200704           // 64*56*56

typedef unsigned long long u64_t;

// ---------------- device scratch ----------------
__device__ float g_qkv[(size_t)NPIX * 384];
__device__ float g_o[(size_t)NPIX * 128];
__device__ float g_x1[(size_t)NPIX * 128];
__device__ float g_h[(size_t)NPIX * 512];
__device__ float g_bias16[13 * 13 * 4];
__device__ float g_scale[4];
__device__ float g_qkvbias[384];

// ---------------- helpers ----------------
__device__ __forceinline__ float2 ffma2(float2 a, float2 b, float2 c) {
    u64_t au = *reinterpret_cast<u64_t*>(&a);
    u64_t bu = *reinterpret_cast<u64_t*>(&b);
    u64_t cu = *reinterpret_cast<u64_t*>(&c);
    u64_t du;
    asm("fma.rn.f32x2 %0, %1, %2, %3;" : "=l"(du) : "l"(au), "l"(bu), "l"(cu));
    return *reinterpret_cast<float2*>(&du);
}

__device__ __forceinline__ void cp_async16(void* smem_dst, const void* gmem_src) {
    unsigned sa = (unsigned)__cvta_generic_to_shared(smem_dst);
    asm volatile("cp.async.cg.shared.global [%0], [%1], 16;" :: "r"(sa), "l"(gmem_src));
}
__device__ __forceinline__ void cp_async_commit() {
    asm volatile("cp.async.commit_group;");
}
__device__ __forceinline__ void cp_async_wait_all() {
    asm volatile("cp.async.wait_group 0;");
}

__device__ __forceinline__ unsigned tf32_of(float f) {
    unsigned u;
    asm("cvt.rna.tf32.f32 %0, %1;" : "=r"(u) : "f"(f));
    return u;
}

__device__ __forceinline__ void mma_tf32(float d[4], const unsigned a[4],
                                         const unsigned b[2], const float c[4]) {
    asm("mma.sync.aligned.m16n8k8.row.col.f32.tf32.tf32.f32 "
        "{%0,%1,%2,%3}, {%4,%5,%6,%7}, {%8,%9}, {%10,%11,%12,%13};"
        : "=f"(d[0]), "=f"(d[1]), "=f"(d[2]), "=f"(d[3])
        : "r"(a[0]), "r"(a[1]), "r"(a[2]), "r"(a[3]),
          "r"(b[0]), "r"(b[1]),
          "f"(c[0]), "f"(c[1]), "f"(c[2]), "f"(c[3]));
}

__device__ __forceinline__ float gelu_exact(float z) {
    return 0.5f * z * (1.0f + erff(z * 0.7071067811865475f));
}

__device__ __forceinline__ size_t scatter_off(int r) {
    unsigned r_ = (unsigned)r;
    unsigned win = r_ / 49u, p = r_ - win * 49u;
    unsigned b = win >> 6, wloc = win & 63u, wr = wloc >> 3, wc = wloc & 7u;
    unsigned ii = p / 7u, jj = p - ii * 7u;
    unsigned sr = wr * 7 + ii + 3; if (sr >= 56) sr -= 56;
    unsigned sc = wc * 7 + jj + 3; if (sc >= 56) sc -= 56;
    return ((size_t)((b * 56 + sr) * 56 + sc)) * 128;
}

// store float4 pair as tf32 bit patterns (2 x STS.128)
__device__ __forceinline__ void sts_tf32x8(float* dst, float4 a, float4 b) {
    uint4 u0, u1;
    u0.x = tf32_of(a.x); u0.y = tf32_of(a.y); u0.z = tf32_of(a.z); u0.w = tf32_of(a.w);
    u1.x = tf32_of(b.x); u1.y = tf32_of(b.y); u1.z = tf32_of(b.z); u1.w = tf32_of(b.w);
    *reinterpret_cast<uint4*>(dst) = u0;
    *reinterpret_cast<uint4*>(dst + 4) = u1;
}

// ---------------- K1: prep ----------------
__device__ __forceinline__ float rpb_f(float v) {
    float sv = v * (2.0f / 9.0f);
    float s = (sv > 0.f) ? 1.f : ((sv < 0.f) ? -1.f : 0.f);
    return s * log1pf(fabsf(sv)) * (1.0f / 2.0794415416798357f);
}

__global__ void k_prep(const float* __restrict__ logit_scale,
                       const float* __restrict__ rpe_w1,
                       const float* __restrict__ rpe_b1,
                       const float* __restrict__ rpe_w2,
                       const float* __restrict__ q_bias,
                       const float* __restrict__ v_bias) {
    int bid = blockIdx.x, t = threadIdx.x;
    if (bid == 169) {
        if (t < 4) g_scale[t] = expf(fminf(logit_scale[t], logf(100.0f)));
        for (int c = t; c < 384; c += 128)
            g_qkvbias[c] = (c < 128) ? q_bias[c] : (c >= 256 ? v_bias[c - 256] : 0.f);
        return;
    }
    int dy = bid / 13 - 6, dx = bid % 13 - 6;
    float t0 = rpb_f((float)dy), t1 = rpb_f((float)dx);
    float a0 = 0, a1 = 0, a2 = 0, a3 = 0;
    for (int k = t; k < 512; k += 128) {
        float hsum = fmaf(t0, rpe_w1[k], fmaf(t1, rpe_w1[512 + k], rpe_b1[k]));
        if (hsum > 0.f) {
            const float* w2r = rpe_w2 + k * 4;
            a0 = fmaf(hsum, w2r[0], a0);
            a1 = fmaf(hsum, w2r[1], a1);
            a2 = fmaf(hsum, w2r[2], a2);
            a3 = fmaf(hsum, w2r[3], a3);
        }
    }
    #pragma unroll
    for (int o = 16; o; o >>= 1) {
        a0 += __shfl_xor_sync(0xffffffffu, a0, o);
        a1 += __shfl_xor_sync(0xffffffffu, a1, o);
        a2 += __shfl_xor_sync(0xffffffffu, a2, o);
        a3 += __shfl_xor_sync(0xffffffffu, a3, o);
    }
    __shared__ float red[4][4];
    int w = t >> 5;
    if ((t & 31) == 0) { red[w][0] = a0; red[w][1] = a1; red[w][2] = a2; red[w][3] = a3; }
    __syncthreads();
    if (t < 4) {
        float s = red[0][t] + red[1][t] + red[2][t] + red[3][t];
        g_bias16[bid * 4 + t] = 16.f / (1.f + expf(-s));
    }
}

// =================================================================
// A-resident tf32 GEMM (K=128, N>128): qkv / fc1   (R12 config)
// EPI: 0 = bias ; 2 = bias + gelu
// =================================================================
#define ARS 132
#define BRS 136
#define SM_ARES (128*ARS*4 + 2*16*BRS*4)

template<int N, int EPI>
__global__ void __launch_bounds__(256, 2) k_gemm_ares(
    const float* __restrict__ A, const float* __restrict__ Bm,
    const float* __restrict__ bias, float* __restrict__ out)
{
    extern __shared__ float smdyn[];
    float* Asm = smdyn;
    float* Bs0 = Asm + 128 * ARS;
    float* Bs1 = Bs0 + 16 * BRS;

    int t = threadIdx.x;
    int lane = t & 31, warp = t >> 5;
    int wm = warp >> 1, wn = warp & 1;
    int gid = lane >> 2, tig = lane & 3;
    int bm = blockIdx.x * 128;

    {
        const float* Ap = A + (size_t)(bm + (t >> 1)) * 128 + (t & 1) * 64;
        float* as = Asm + (t >> 1) * ARS + (t & 1) * 64;
        #pragma unroll
        for (int j = 0; j < 16; ++j) cp_async16(as + j * 4, Ap + j * 4);
        cp_async_commit();
        cp_async_wait_all();
        #pragma unroll 8
        for (int i = 0; i < 64; ++i) as[i] = __uint_as_float(tf32_of(as[i]));
    }

    int bk = t >> 4, bc = (t & 15) * 8;
    {
        const float* Bp = Bm + (size_t)bk * N + bc;
        float4 r0 = *(const float4*)Bp;
        float4 r1 = *(const float4*)(Bp + 4);
        sts_tf32x8(Bs0 + bk * BRS + bc, r0, r1);
    }
    __syncthreads();

    float acc[2][8][4];
    #pragma unroll
    for (int i = 0; i < 2; ++i)
        #pragma unroll
        for (int j = 0; j < 8; ++j)
            #pragma unroll
            for (int e = 0; e < 4; ++e) acc[i][j][e] = 0.f;

    const int T = (N / 128) * 8;
    float4 r0, r1;
    #pragma unroll 1
    for (int st = 0; st < T; ++st) {
        float* bsC = (st & 1) ? Bs1 : Bs0;
        float* bsN = (st & 1) ? Bs0 : Bs1;
        if (st + 1 < T) {
            int nt1 = (st + 1) >> 3, s1 = (st + 1) & 7;
            const float* Bp = Bm + (size_t)(s1 * 16 + bk) * N + nt1 * 128 + bc;
            r0 = *(const float4*)Bp;
            r1 = *(const float4*)(Bp + 4);
        }
        int kb0 = (st & 7) * 16;
        #pragma unroll
        for (int kb = 0; kb < 16; kb += 8) {
            unsigned af[2][4];
            #pragma unroll
            for (int i = 0; i < 2; ++i) {
                const float* ab = &Asm[(wm * 32 + i * 16 + gid) * ARS + kb0 + kb + tig];
                af[i][0] = __float_as_uint(ab[0]);
                af[i][1] = __float_as_uint(ab[8 * ARS]);
                af[i][2] = __float_as_uint(ab[4]);
                af[i][3] = __float_as_uint(ab[8 * ARS + 4]);
            }
            #pragma unroll
            for (int j = 0; j < 8; ++j) {
                unsigned bf[2];
                int ncol = wn * 64 + j * 8 + gid;
                bf[0] = __float_as_uint(bsC[(kb + tig) * BRS + ncol]);
                bf[1] = __float_as_uint(bsC[(kb + tig + 4) * BRS + ncol]);
                mma_tf32(acc[0][j], af[0], bf, acc[0][j]);
                mma_tf32(acc[1][j], af[1], bf, acc[1][j]);
            }
        }

        if ((st & 7) == 7) {
            int nt = st >> 3;
            int cb = nt * 128 + wn * 64;
            #pragma unroll
            for (int i = 0; i < 2; ++i) {
                int rr0 = bm + wm * 32 + i * 16 + gid;
                #pragma unroll
                for (int j = 0; j < 8; ++j) {
                    int c = cb + j * 8 + tig * 2;
                    float2 bb = *(const float2*)(bias + c);
                    float2 v0 = make_float2(acc[i][j][0] + bb.x, acc[i][j][1] + bb.y);
                    float2 v1 = make_float2(acc[i][j][2] + bb.x, acc[i][j][3] + bb.y);
                    if (EPI == 2) {
                        v0.x = gelu_exact(v0.x); v0.y = gelu_exact(v0.y);
                        v1.x = gelu_exact(v1.x); v1.y = gelu_exact(v1.y);
                    }
                    *(float2*)(out + (size_t)rr0 * N + c) = v0;
                    *(float2*)(out + (size_t)(rr0 + 8) * N + c) = v1;
                }
            }
            if (st + 1 < T) {
                #pragma unroll
                for (int i = 0; i < 2; ++i)
                    #pragma unroll
                    for (int j = 0; j < 8; ++j)
                        #pragma unroll
                        for (int e = 0; e < 4; ++e) acc[i][j][e] = 0.f;
            }
        }
        if (st + 1 < T) {
            sts_tf32x8(bsN + bk * BRS + bc, r0, r1);
            __syncthreads();
        }
    }
}

// =================================================================
// streaming tf32 GEMM (R12 config): BM=128, BN=128, 2-stage cp.async,
// per-use cvt in mainloop.
// EPI 0 = bias ; 3 = bias+LN+residual (row order) ; 4 = bias+LN+residual (scatter)
// =================================================================
#define AS 20
#define BSo 136

template<int K, int N, int EPI>
__global__ void __launch_bounds__(256, 2) k_gemm_tc(
    const float* __restrict__ A, const float* __restrict__ Bm,
    const float* __restrict__ bias, float* __restrict__ out,
    const float* __restrict__ resid, const float* __restrict__ lng,
    const float* __restrict__ lnb)
{
    __shared__ __align__(16) float Asm[2][128 * AS];
    __shared__ __align__(16) float Bs[2][16 * BSo];
    __shared__ float ssum[128][2], ssq[128][2];
    int t = threadIdx.x;
    int lane = t & 31, warp = t >> 5;
    int wm = warp >> 1, wn = warp & 1;
    int gid = lane >> 2, tig = lane & 3;
    int bm = blockIdx.x * 128, bn = blockIdx.y * 128;

    int ar0 = t >> 1, ac0 = (t & 1) * 8;
    int bk = t >> 4, bc = (t & 15) * 8;

    const float* Ap = A + (size_t)(bm + ar0) * K + ac0;
    const float* Bp = Bm + (size_t)bk * N + bn + bc;

    cp_async16(&Asm[0][ar0 * AS + ac0], Ap);
    cp_async16(&Asm[0][ar0 * AS + ac0 + 4], Ap + 4);
    cp_async16(&Bs[0][bk * BSo + bc], Bp);
    cp_async16(&Bs[0][bk * BSo + bc + 4], Bp + 4);
    cp_async_commit();
    cp_async_wait_all();
    __syncthreads();

    float acc[2][8][4];
    #pragma unroll
    for (int i = 0; i < 2; ++i)
        #pragma unroll
        for (int j = 0; j < 8; ++j)
            #pragma unroll
            for (int e = 0; e < 4; ++e) acc[i][j][e] = 0.f;

    const int S = K / 16;
    #pragma unroll 1
    for (int s = 0; s < S; ++s) {
        int buf = s & 1;
        if (s + 1 < S) {
            int nb = buf ^ 1;
            const float* a0 = Ap + (s + 1) * 16;
            const float* b0 = Bp + (size_t)(s + 1) * 16 * N;
            cp_async16(&Asm[nb][ar0 * AS + ac0], a0);
            cp_async16(&Asm[nb][ar0 * AS + ac0 + 4], a0 + 4);
            cp_async16(&Bs[nb][bk * BSo + bc], b0);
            cp_async16(&Bs[nb][bk * BSo + bc + 4], b0 + 4);
            cp_async_commit();
        }
        #pragma unroll
        for (int kb = 0; kb < 16; kb += 8) {
            unsigned af[2][4];
            #pragma unroll
            for (int i = 0; i < 2; ++i) {
                const float* ab = &Asm[buf][(wm * 32 + i * 16 + gid) * AS + kb + tig];
                af[i][0] = tf32_of(ab[0]);
                af[i][1] = tf32_of(ab[8 * AS]);
                af[i][2] = tf32_of(ab[4]);
                af[i][3] = tf32_of(ab[8 * AS + 4]);
            }
            #pragma unroll
            for (int j = 0; j < 8; ++j) {
                unsigned bf[2];
                int ncol = wn * 64 + j * 8 + gid;
                bf[0] = tf32_of(Bs[buf][(kb + tig) * BSo + ncol]);
                bf[1] = tf32_of(Bs[buf][(kb + tig + 4) * BSo + ncol]);
                mma_tf32(acc[0][j], af[0], bf, acc[0][j]);
                mma_tf32(acc[1][j], af[1], bf, acc[1][j]);
            }
        }
        if (s + 1 < S) {
            cp_async_wait_all();
            __syncthreads();
        }
    }

    if (EPI == 0) {
        #pragma unroll
        for (int i = 0; i < 2; ++i) {
            int r0 = bm + wm * 32 + i * 16 + gid;
            #pragma unroll
            for (int j = 0; j < 8; ++j) {
                int c = bn + wn * 64 + j * 8 + tig * 2;
                float2 bb = *(const float2*)(bias + c);
                float2 v0 = make_float2(acc[i][j][0] + bb.x, acc[i][j][1] + bb.y);
                float2 v1 = make_float2(acc[i][j][2] + bb.x, acc[i][j][3] + bb.y);
                *(float2*)(out + (size_t)r0 * N + c) = v0;
                *(float2*)(out + (size_t)(r0 + 8) * N + c) = v1;
            }
        }
    } else {
        __syncthreads();
        #pragma unroll
        for (int i = 0; i < 2; ++i) {
            float ps0 = 0.f, pq0 = 0.f, ps1 = 0.f, pq1 = 0.f;
            #pragma unroll
            for (int j = 0; j < 8; ++j) {
                int c = wn * 64 + j * 8 + tig * 2;
                float2 bb = *(const float2*)(bias + c);
                acc[i][j][0] += bb.x; acc[i][j][1] += bb.y;
                acc[i][j][2] += bb.x; acc[i][j][3] += bb.y;
                ps0 += acc[i][j][0] + acc[i][j][1];
                pq0 += acc[i][j][0] * acc[i][j][0] + acc[i][j][1] * acc[i][j][1];
                ps1 += acc[i][j][2] + acc[i][j][3];
                pq1 += acc[i][j][2] * acc[i][j][2] + acc[i][j][3] * acc[i][j][3];
            }
            #pragma unroll
            for (int o = 1; o < 4; o <<= 1) {
                ps0 += __shfl_xor_sync(0xffffffffu, ps0, o);
                pq0 += __shfl_xor_sync(0xffffffffu, pq0, o);
                ps1 += __shfl_xor_sync(0xffffffffu, ps1, o);
                pq1 += __shfl_xor_sync(0xffffffffu, pq1, o);
            }
            if (tig == 0) {
                int ra = wm * 32 + i * 16 + gid;
                ssum[ra][wn] = ps0; ssq[ra][wn] = pq0;
                ssum[ra + 8][wn] = ps1; ssq[ra + 8][wn] = pq1;
            }
        }
        __syncthreads();
        #pragma unroll
        for (int i = 0; i < 2; ++i) {
            int ra = wm * 32 + i * 16 + gid;
            #pragma unroll
            for (int h = 0; h < 2; ++h) {
                int row = ra + h * 8;
                float s = ssum[row][0] + ssum[row][1];
                float q2 = ssq[row][0] + ssq[row][1];
                float m = s * (1.f / 128.f);
                float var = q2 * (1.f / 128.f) - m * m;
                float inv = rsqrtf(var + 1e-3f);
                size_t off = (EPI == 4) ? scatter_off(bm + row) : (size_t)(bm + row) * 128;
                #pragma unroll
                for (int j = 0; j < 8; ++j) {
                    int c = wn * 64 + j * 8 + tig * 2;
                    float2 gg = *(const float2*)(lng + c);
                    float2 be = *(const float2*)(lnb + c);
                    float2 xr = *(const float2*)(resid + off + c);
                    float e0 = acc[i][j][2 * h], e1 = acc[i][j][2 * h + 1];
                    float2 o2;
                    o2.x = xr.x + (e0 - m) * inv * gg.x + be.x;
                    o2.y = xr.y + (e1 - m) * inv * gg.y + be.y;
                    *(float2*)(out + off + c) = o2;
                }
            }
        }
    }
}

// ---------------- K-core: per-(window, head) attention ----------------
// R12 structure + float4 gather.
#define HQS 36

__global__ void __launch_bounds__(128) k_core(const float* __restrict__ mask) {
    __shared__ float q[NTOK * HQS];
    __shared__ float kk[NTOK * HQS];
    __shared__ float v[NTOK * 32];
    __shared__ float at[NTOK * NTOK];
    __shared__ int pix[NTOK];

    int t = threadIdx.x;
    int lane = t & 31, warp = t >> 5;
    int win = blockIdx.x, h = blockIdx.y;
    int b = win >> 6, wloc = win & 63, wr = wloc >> 3, wc = wloc & 7;

    if (t < NTOK) {
        int i = t / WS, j = t % WS;
        int sr = (wr * WS + i + 3) % HW;
        int sc = (wc * WS + j + 3) % HW;
        pix[t] = (b * HW + sr) * HW + sc;
    }
    __syncthreads();

    // gather q/k/v head slices via float4 (49 rows x 8 float4 each)
    for (int idx = t; idx < NTOK * 8; idx += 128) {
        int p = idx >> 3, c4 = idx & 7;
        const float* base = g_qkv + (size_t)pix[p] * 384 + h * 32 + c4 * 4;
        *(float4*)(q + p * HQS + c4 * 4)  = *(const float4*)(base);
        *(float4*)(kk + p * HQS + c4 * 4) = *(const float4*)(base + 128);
        *(float4*)(v + p * 32 + c4 * 4)   = *(const float4*)(base + 256);
    }
    __syncthreads();

    if (t < 2 * NTOK) {
        float4* b4 = (float4*)((t < NTOK) ? (q + t * HQS) : (kk + (t - NTOK) * HQS));
        float s = 0.f;
        #pragma unroll
        for (int d = 0; d < 8; ++d) {
            float4 vv = b4[d];
            s += vv.x * vv.x + vv.y * vv.y + vv.z * vv.z + vv.w * vv.w;
        }
        float inv = rsqrtf(fmaxf(s, 1e-12f));
        #pragma unroll
        for (int d = 0; d < 8; ++d) {
            float4 vv = b4[d];
            vv.x *= inv; vv.y *= inv; vv.z *= inv; vv.w *= inv;
            b4[d] = vv;
        }
    }
    __syncthreads();

    // scores: 2x2 output tiles over the 49x49 matrix (625 tiles)
    float scal = g_scale[h];
    const float* mw = mask + (size_t)wloc * (NTOK * NTOK);
    for (int idx = t; idx < 625; idx += 128) {
        int tp = idx / 25, tq = idx - tp * 25;
        int p0 = tp * 2, q0 = tq * 2;
        int p1 = (p0 + 1 < NTOK) ? p0 + 1 : p0;
        int q1 = (q0 + 1 < NTOK) ? q0 + 1 : q0;
        const float4* qa = (const float4*)(q + p0 * HQS);
        const float4* qb = (const float4*)(q + p1 * HQS);
        const float4* ka = (const float4*)(kk + q0 * HQS);
        const float4* kb = (const float4*)(kk + q1 * HQS);
        float2 c00 = make_float2(0.f, 0.f), c01 = make_float2(0.f, 0.f);
        float2 c10 = make_float2(0.f, 0.f), c11 = make_float2(0.f, 0.f);
        #pragma unroll
        for (int d = 0; d < 8; ++d) {
            float4 qv0 = qa[d], qv1 = qb[d], kv0 = ka[d], kv1 = kb[d];
            float2 q0l = make_float2(qv0.x, qv0.y), q0h = make_float2(qv0.z, qv0.w);
            float2 q1l = make_float2(qv1.x, qv1.y), q1h = make_float2(qv1.z, qv1.w);
            float2 k0l = make_float2(kv0.x, kv0.y), k0h = make_float2(kv0.z, kv0.w);
            float2 k1l = make_float2(kv1.x, kv1.y), k1h = make_float2(kv1.z, kv1.w);
            c00 = ffma2(q0l, k0l, c00); c00 = ffma2(q0h, k0h, c00);
            c01 = ffma2(q0l, k1l, c01); c01 = ffma2(q0h, k1h, c01);
            c10 = ffma2(q1l, k0l, c10); c10 = ffma2(q1h, k0h, c10);
            c11 = ffma2(q1l, k1l, c11); c11 = ffma2(q1h, k1h, c11);
        }
        int py0 = p0 / WS, px0 = p0 - py0 * WS;
        int py1 = p1 / WS, px1 = p1 - py1 * WS;
        int qy0 = q0 / WS, qx0 = q0 - qy0 * WS;
        int qy1 = q1 / WS, qx1 = q1 - qy1 * WS;
        at[p0 * NTOK + q0] = fmaf(c00.x + c00.y, scal,
            g_bias16[((py0 - qy0 + 6) * 13 + px0 - qx0 + 6) * 4 + h] + mw[p0 * NTOK + q0]);
        if (q1 != q0)
            at[p0 * NTOK + q1] = fmaf(c01.x + c01.y, scal,
                g_bias16[((py0 - qy1 + 6) * 13 + px0 - qx1 + 6) * 4 + h] + mw[p0 * NTOK + q1]);
        if (p1 != p0) {
            at[p1 * NTOK + q0] = fmaf(c10.x + c10.y, scal,
                g_bias16[((py1 - qy0 + 6) * 13 + px1 - qx0 + 6) * 4 + h] + mw[p1 * NTOK + q0]);
            if (q1 != q0)
                at[p1 * NTOK + q1] = fmaf(c11.x + c11.y, scal,
                    g_bias16[((py1 - qy1 + 6) * 13 + px1 - qx1 + 6) * 4 + h] + mw[p1 * NTOK + q1]);
        }
    }
    __syncthreads();

    for (int row = warp; row < NTOK; row += 4) {
        float* r = at + row * NTOK;
        float v0 = r[lane < NTOK ? lane : 0];
        if (lane >= NTOK) v0 = -1e30f;
        float v1 = (lane + 32 < NTOK) ? r[lane + 32] : -1e30f;
        float m = fmaxf(v0, v1);
        #pragma unroll
        for (int o = 16; o; o >>= 1) m = fmaxf(m, __shfl_xor_sync(0xffffffffu, m, o));
        float e0 = (lane < NTOK) ? expf(v0 - m) : 0.f;
        float e1 = (lane + 32 < NTOK) ? expf(v1 - m) : 0.f;
        float s = e0 + e1;
        #pragma unroll
        for (int o = 16; o; o >>= 1) s += __shfl_xor_sync(0xffffffffu, s, o);
        float inv = 1.f / s;
        if (lane < NTOK) r[lane] = e0 * inv;
        if (lane + 32 < NTOK) r[lane + 32] = e1 * inv;
    }
    __syncthreads();

    // o = attn @ v, 2 p-rows share each v load (400 tasks = 25 pairs x 16 cols)
    const float2* v2 = (const float2*)v;
    for (int idx = t; idx < 400; idx += 128) {
        int pp = idx >> 4, cp = idx & 15;
        int p0 = pp * 2, p1 = p0 + 1;
        bool has1 = (p1 < NTOK);
        const float* ar0 = at + p0 * NTOK;
        const float* ar1 = at + (has1 ? p1 : p0) * NTOK;
        float2 acc0 = make_float2(0.f, 0.f), acc1 = make_float2(0.f, 0.f);
        #pragma unroll 7
        for (int qq = 0; qq < NTOK; ++qq) {
            float2 vv = v2[qq * 16 + cp];
            float a0 = ar0[qq], a1 = ar1[qq];
            acc0 = ffma2(make_float2(a0, a0), vv, acc0);
            acc1 = ffma2(make_float2(a1, a1), vv, acc1);
        }
        *(float2*)(g_o + ((size_t)win * NTOK + p0) * 128 + h * 32 + cp * 2) = acc0;
        if (has1)
            *(float2*)(g_o + ((size_t)win * NTOK + p1) * 128 + h * 32 + cp * 2) = acc1;
    }
}

// ---------------- launch ----------------
extern "C" void kernel_launch(void* const* d_in, const int* in_sizes, int n_in,
                              void* d_out, int out_size) {
    const float* x           = (const float*)d_in[0];
    const float* mask        = (const float*)d_in[1];
    const float* norm1_g     = (const float*)d_in[2];
    const float* norm1_b     = (const float*)d_in[3];
    const float* qkv_w       = (const float*)d_in[4];
    const float* q_bias      = (const float*)d_in[5];
    const float* v_bias      = (const float*)d_in[6];
    const float* logit_scale = (const float*)d_in[7];
    const float* rpe_w1      = (const float*)d_in[8];
    const float* rpe_b1      = (const float*)d_in[9];
    const float* rpe_w2      = (const float*)d_in[10];
    const float* proj_w      = (const float*)d_in[11];
    const float* proj_b      = (const float*)d_in[12];
    const float* norm2_g     = (const float*)d_in[13];
    const float* norm2_b     = (const float*)d_in[14];
    const float* fc1_w       = (const float*)d_in[15];
    const float* fc1_b       = (const float*)d_in[16];
    const float* fc2_w       = (const float*)d_in[17];
    const float* fc2_b       = (const float*)d_in[18];
    float* out = (float*)d_out;

    float *p_qkv, *p_o, *p_x1, *p_h, *p_qb;
    cudaGetSymbolAddress((void**)&p_qkv, g_qkv);
    cudaGetSymbolAddress((void**)&p_o,   g_o);
    cudaGetSymbolAddress((void**)&p_x1,  g_x1);
    cudaGetSymbolAddress((void**)&p_h,   g_h);
    cudaGetSymbolAddress((void**)&p_qb,  g_qkvbias);

    cudaFuncSetAttribute(k_gemm_ares<384, 0>, cudaFuncAttributeMaxDynamicSharedMemorySize, SM_ARES);
    cudaFuncSetAttribute(k_gemm_ares<512, 2>, cudaFuncAttributeMaxDynamicSharedMemorySize, SM_ARES);

    k_prep<<<170, 128>>>(logit_scale, rpe_w1, rpe_b1, rpe_w2, q_bias, v_bias);

    k_gemm_ares<384, 0><<<NPIX / 128, 256, SM_ARES>>>(x, qkv_w, p_qb, p_qkv);

    dim3 gc(NWIN_TOT, 4);
    k_core<<<gc, 128>>>(mask);

    dim3 gp(NPIX / 128, 1);
    k_gemm_tc<128, 128, 4><<<gp, 256>>>(p_o, proj_w, proj_b, p_x1,
                                        x, norm1_g, norm1_b);

    k_gemm_ares<512, 2><<<NPIX / 128, 256, SM_ARES>>>(p_x1, fc1_w, fc1_b, p_h);

    dim3 g2(NPIX / 128, 1);
    k_gemm_tc<512, 128, 3><<<g2, 256>>>(p_h, fc2_w, fc2_b, out,
                                        p_x1, norm2_g, norm2_b);
}

// round 16
// speedup vs baseline: 1.1420x; 1.0649x over previous
#include <cuda_runtime.h>
#include <math.h>

#define HW 56
#define CDIM 128
#define WS 7
#define NTOK 49
#define NWIN_TOT 4096
#define NPIX 200704           // 64*56*56

typedef unsigned long long u64_t;

// ---------------- device scratch ----------------
__device__ float g_qkv[(size_t)NPIX * 384];
__device__ float g_o[(size_t)NPIX * 128];        // tf32-rounded bits
__device__ float g_x1[(size_t)NPIX * 128];       // full fp32 (residual source)
__device__ float g_h[(size_t)NPIX * 512];        // tf32-rounded bits
__device__ float g_bias16[13 * 13 * 4];
__device__ float g_scale[4];
__device__ float g_qkvbias[384];
// tf32-rounded weight copies
__device__ float g_wqkv[128 * 384];
__device__ float g_wproj[128 * 128];
__device__ float g_wfc1[128 * 512];
__device__ float g_wfc2[512 * 128];

// ---------------- helpers ----------------
__device__ __forceinline__ float2 ffma2(float2 a, float2 b, float2 c) {
    u64_t au = *reinterpret_cast<u64_t*>(&a);
    u64_t bu = *reinterpret_cast<u64_t*>(&b);
    u64_t cu = *reinterpret_cast<u64_t*>(&c);
    u64_t du;
    asm("fma.rn.f32x2 %0, %1, %2, %3;" : "=l"(du) : "l"(au), "l"(bu), "l"(cu));
    return *reinterpret_cast<float2*>(&du);
}

__device__ __forceinline__ void cp_async16(void* smem_dst, const void* gmem_src) {
    unsigned sa = (unsigned)__cvta_generic_to_shared(smem_dst);
    asm volatile("cp.async.cg.shared.global [%0], [%1], 16;" :: "r"(sa), "l"(gmem_src));
}
__device__ __forceinline__ void cp_async_commit() {
    asm volatile("cp.async.commit_group;");
}
__device__ __forceinline__ void cp_async_wait_all() {
    asm volatile("cp.async.wait_group 0;");
}

__device__ __forceinline__ unsigned tf32_of(float f) {
    unsigned u;
    asm("cvt.rna.tf32.f32 %0, %1;" : "=r"(u) : "f"(f));
    return u;
}
__device__ __forceinline__ float tf32r(float f) {
    return __uint_as_float(tf32_of(f));
}

__device__ __forceinline__ void mma_tf32(float d[4], const unsigned a[4],
                                         const unsigned b[2], const float c[4]) {
    asm("mma.sync.aligned.m16n8k8.row.col.f32.tf32.tf32.f32 "
        "{%0,%1,%2,%3}, {%4,%5,%6,%7}, {%8,%9}, {%10,%11,%12,%13};"
        : "=f"(d[0]), "=f"(d[1]), "=f"(d[2]), "=f"(d[3])
        : "r"(a[0]), "r"(a[1]), "r"(a[2]), "r"(a[3]),
          "r"(b[0]), "r"(b[1]),
          "f"(c[0]), "f"(c[1]), "f"(c[2]), "f"(c[3]));
}

__device__ __forceinline__ float gelu_exact(float z) {
    return 0.5f * z * (1.0f + erff(z * 0.7071067811865475f));
}

__device__ __forceinline__ size_t scatter_off(int r) {
    unsigned r_ = (unsigned)r;
    unsigned win = r_ / 49u, p = r_ - win * 49u;
    unsigned b = win >> 6, wloc = win & 63u, wr = wloc >> 3, wc = wloc & 7u;
    unsigned ii = p / 7u, jj = p - ii * 7u;
    unsigned sr = wr * 7 + ii + 3; if (sr >= 56) sr -= 56;
    unsigned sc = wc * 7 + jj + 3; if (sc >= 56) sc -= 56;
    return ((size_t)((b * 56 + sr) * 56 + sc)) * 128;
}

// ---------------- K0: round weights to tf32 bits ----------------
__global__ void k_round(const float* __restrict__ src, float* __restrict__ dst, int n) {
    int i = blockIdx.x * 256 + threadIdx.x;
    if (i < n) dst[i] = tf32r(src[i]);
}

// ---------------- K1: prep ----------------
__device__ __forceinline__ float rpb_f(float v) {
    float sv = v * (2.0f / 9.0f);
    float s = (sv > 0.f) ? 1.f : ((sv < 0.f) ? -1.f : 0.f);
    return s * log1pf(fabsf(sv)) * (1.0f / 2.0794415416798357f);
}

__global__ void k_prep(const float* __restrict__ logit_scale,
                       const float* __restrict__ rpe_w1,
                       const float* __restrict__ rpe_b1,
                       const float* __restrict__ rpe_w2,
                       const float* __restrict__ q_bias,
                       const float* __restrict__ v_bias) {
    int bid = blockIdx.x, t = threadIdx.x;
    if (bid == 169) {
        if (t < 4) g_scale[t] = expf(fminf(logit_scale[t], logf(100.0f)));
        for (int c = t; c < 384; c += 128)
            g_qkvbias[c] = (c < 128) ? q_bias[c] : (c >= 256 ? v_bias[c - 256] : 0.f);
        return;
    }
    int dy = bid / 13 - 6, dx = bid % 13 - 6;
    float t0 = rpb_f((float)dy), t1 = rpb_f((float)dx);
    float a0 = 0, a1 = 0, a2 = 0, a3 = 0;
    for (int k = t; k < 512; k += 128) {
        float hsum = fmaf(t0, rpe_w1[k], fmaf(t1, rpe_w1[512 + k], rpe_b1[k]));
        if (hsum > 0.f) {
            const float* w2r = rpe_w2 + k * 4;
            a0 = fmaf(hsum, w2r[0], a0);
            a1 = fmaf(hsum, w2r[1], a1);
            a2 = fmaf(hsum, w2r[2], a2);
            a3 = fmaf(hsum, w2r[3], a3);
        }
    }
    #pragma unroll
    for (int o = 16; o; o >>= 1) {
        a0 += __shfl_xor_sync(0xffffffffu, a0, o);
        a1 += __shfl_xor_sync(0xffffffffu, a1, o);
        a2 += __shfl_xor_sync(0xffffffffu, a2, o);
        a3 += __shfl_xor_sync(0xffffffffu, a3, o);
    }
    __shared__ float red[4][4];
    int w = t >> 5;
    if ((t & 31) == 0) { red[w][0] = a0; red[w][1] = a1; red[w][2] = a2; red[w][3] = a3; }
    __syncthreads();
    if (t < 4) {
        float s = red[0][t] + red[1][t] + red[2][t] + red[3][t];
        g_bias16[bid * 4 + t] = 16.f / (1.f + expf(-s));
    }
}

// =================================================================
// A-resident tf32 GEMM (K=128, N>128): qkv / fc1
// B pre-rounded -> plain cp.async staging, zero staging cvt.
// EPI: 0 = bias (qkv, full fp32 out) ; 2 = bias + gelu + tf32-round (fc1)
// =================================================================
#define ARS 132
#define BRS 136
#define SM_ARES (128*ARS*4 + 2*16*BRS*4)

template<int N, int EPI>
__global__ void __launch_bounds__(256, 2) k_gemm_ares(
    const float* __restrict__ A, const float* __restrict__ Bm,
    const float* __restrict__ bias, float* __restrict__ out)
{
    extern __shared__ float smdyn[];
    float* Asm = smdyn;
    float* Bs0 = Asm + 128 * ARS;
    float* Bs1 = Bs0 + 16 * BRS;

    int t = threadIdx.x;
    int lane = t & 31, warp = t >> 5;
    int wm = warp >> 1, wn = warp & 1;
    int gid = lane >> 2, tig = lane & 3;
    int bm = blockIdx.x * 128;

    int bk = t >> 4, bc = (t & 15) * 8;

    // A tile load (cvt once — A may be full fp32)
    {
        const float* Ap = A + (size_t)(bm + (t >> 1)) * 128 + (t & 1) * 64;
        float* as = Asm + (t >> 1) * ARS + (t & 1) * 64;
        #pragma unroll
        for (int j = 0; j < 16; ++j) cp_async16(as + j * 4, Ap + j * 4);
        cp_async_commit();
    }
    // B stage 0 (pre-rounded -> raw cp.async)
    {
        const float* Bp = Bm + (size_t)bk * N + bc;
        cp_async16(Bs0 + bk * BRS + bc, Bp);
        cp_async16(Bs0 + bk * BRS + bc + 4, Bp + 4);
        cp_async_commit();
    }
    cp_async_wait_all();
    {
        float* as = Asm + (t >> 1) * ARS + (t & 1) * 64;
        #pragma unroll 8
        for (int i = 0; i < 64; ++i) as[i] = tf32r(as[i]);
    }
    __syncthreads();

    float acc[2][8][4];
    #pragma unroll
    for (int i = 0; i < 2; ++i)
        #pragma unroll
        for (int j = 0; j < 8; ++j)
            #pragma unroll
            for (int e = 0; e < 4; ++e) acc[i][j][e] = 0.f;

    const int T = (N / 128) * 8;
    #pragma unroll 1
    for (int st = 0; st < T; ++st) {
        float* bsC = (st & 1) ? Bs1 : Bs0;
        float* bsN = (st & 1) ? Bs0 : Bs1;
        if (st + 1 < T) {
            int nt1 = (st + 1) >> 3, s1 = (st + 1) & 7;
            const float* Bp = Bm + (size_t)(s1 * 16 + bk) * N + nt1 * 128 + bc;
            cp_async16(bsN + bk * BRS + bc, Bp);
            cp_async16(bsN + bk * BRS + bc + 4, Bp + 4);
            cp_async_commit();
        }
        int kb0 = (st & 7) * 16;
        #pragma unroll
        for (int kb = 0; kb < 16; kb += 8) {
            unsigned af[2][4];
            #pragma unroll
            for (int i = 0; i < 2; ++i) {
                const float* ab = &Asm[(wm * 32 + i * 16 + gid) * ARS + kb0 + kb + tig];
                af[i][0] = __float_as_uint(ab[0]);
                af[i][1] = __float_as_uint(ab[8 * ARS]);
                af[i][2] = __float_as_uint(ab[4]);
                af[i][3] = __float_as_uint(ab[8 * ARS + 4]);
            }
            #pragma unroll
            for (int j = 0; j < 8; ++j) {
                unsigned bf[2];
                int ncol = wn * 64 + j * 8 + gid;
                bf[0] = __float_as_uint(bsC[(kb + tig) * BRS + ncol]);
                bf[1] = __float_as_uint(bsC[(kb + tig + 4) * BRS + ncol]);
                mma_tf32(acc[0][j], af[0], bf, acc[0][j]);
                mma_tf32(acc[1][j], af[1], bf, acc[1][j]);
            }
        }

        if ((st & 7) == 7) {
            int nt = st >> 3;
            int cb = nt * 128 + wn * 64;
            #pragma unroll
            for (int i = 0; i < 2; ++i) {
                int rr0 = bm + wm * 32 + i * 16 + gid;
                #pragma unroll
                for (int j = 0; j < 8; ++j) {
                    int c = cb + j * 8 + tig * 2;
                    float2 bb = *(const float2*)(bias + c);
                    float2 v0 = make_float2(acc[i][j][0] + bb.x, acc[i][j][1] + bb.y);
                    float2 v1 = make_float2(acc[i][j][2] + bb.x, acc[i][j][3] + bb.y);
                    if (EPI == 2) {
                        v0.x = tf32r(gelu_exact(v0.x)); v0.y = tf32r(gelu_exact(v0.y));
                        v1.x = tf32r(gelu_exact(v1.x)); v1.y = tf32r(gelu_exact(v1.y));
                    }
                    *(float2*)(out + (size_t)rr0 * N + c) = v0;
                    *(float2*)(out + (size_t)(rr0 + 8) * N + c) = v1;
                }
            }
            if (st + 1 < T) {
                #pragma unroll
                for (int i = 0; i < 2; ++i)
                    #pragma unroll
                    for (int j = 0; j < 8; ++j)
                        #pragma unroll
                        for (int e = 0; e < 4; ++e) acc[i][j][e] = 0.f;
            }
        }
        if (st + 1 < T) {
            cp_async_wait_all();
            __syncthreads();
        }
    }
}

// =================================================================
// streaming tf32 GEMM: BM=128, BN=128, 2-stage cp.async,
// A and B pre-rounded -> ZERO in-loop cvt.
// EPI 3 = bias+LN+residual (row order) ; 4 = bias+LN+residual (scatter)
// =================================================================
#define AS 20
#define BSo 136

template<int K, int N, int EPI>
__global__ void __launch_bounds__(256, 2) k_gemm_tc(
    const float* __restrict__ A, const float* __restrict__ Bm,
    const float* __restrict__ bias, float* __restrict__ out,
    const float* __restrict__ resid, const float* __restrict__ lng,
    const float* __restrict__ lnb)
{
    __shared__ __align__(16) float Asm[2][128 * AS];
    __shared__ __align__(16) float Bs[2][16 * BSo];
    __shared__ float ssum[128][2], ssq[128][2];
    int t = threadIdx.x;
    int lane = t & 31, warp = t >> 5;
    int wm = warp >> 1, wn = warp & 1;
    int gid = lane >> 2, tig = lane & 3;
    int bm = blockIdx.x * 128, bn = blockIdx.y * 128;

    int ar0 = t >> 1, ac0 = (t & 1) * 8;
    int bk = t >> 4, bc = (t & 15) * 8;

    const float* Ap = A + (size_t)(bm + ar0) * K + ac0;
    const float* Bp = Bm + (size_t)bk * N + bn + bc;

    cp_async16(&Asm[0][ar0 * AS + ac0], Ap);
    cp_async16(&Asm[0][ar0 * AS + ac0 + 4], Ap + 4);
    cp_async16(&Bs[0][bk * BSo + bc], Bp);
    cp_async16(&Bs[0][bk * BSo + bc + 4], Bp + 4);
    cp_async_commit();
    cp_async_wait_all();
    __syncthreads();

    float acc[2][8][4];
    #pragma unroll
    for (int i = 0; i < 2; ++i)
        #pragma unroll
        for (int j = 0; j < 8; ++j)
            #pragma unroll
            for (int e = 0; e < 4; ++e) acc[i][j][e] = 0.f;

    const int S = K / 16;
    #pragma unroll 1
    for (int s = 0; s < S; ++s) {
        int buf = s & 1;
        if (s + 1 < S) {
            int nb = buf ^ 1;
            const float* a0 = Ap + (s + 1) * 16;
            const float* b0 = Bp + (size_t)(s + 1) * 16 * N;
            cp_async16(&Asm[nb][ar0 * AS + ac0], a0);
            cp_async16(&Asm[nb][ar0 * AS + ac0 + 4], a0 + 4);
            cp_async16(&Bs[nb][bk * BSo + bc], b0);
            cp_async16(&Bs[nb][bk * BSo + bc + 4], b0 + 4);
            cp_async_commit();
        }
        #pragma unroll
        for (int kb = 0; kb < 16; kb += 8) {
            unsigned af[2][4];
            #pragma unroll
            for (int i = 0; i < 2; ++i) {
                const float* ab = &Asm[buf][(wm * 32 + i * 16 + gid) * AS + kb + tig];
                af[i][0] = __float_as_uint(ab[0]);
                af[i][1] = __float_as_uint(ab[8 * AS]);
                af[i][2] = __float_as_uint(ab[4]);
                af[i][3] = __float_as_uint(ab[8 * AS + 4]);
            }
            #pragma unroll
            for (int j = 0; j < 8; ++j) {
                unsigned bf[2];
                int ncol = wn * 64 + j * 8 + gid;
                bf[0] = __float_as_uint(Bs[buf][(kb + tig) * BSo + ncol]);
                bf[1] = __float_as_uint(Bs[buf][(kb + tig + 4) * BSo + ncol]);
                mma_tf32(acc[0][j], af[0], bf, acc[0][j]);
                mma_tf32(acc[1][j], af[1], bf, acc[1][j]);
            }
        }
        if (s + 1 < S) {
            cp_async_wait_all();
            __syncthreads();
        }
    }

    __syncthreads();
    #pragma unroll
    for (int i = 0; i < 2; ++i) {
        float ps0 = 0.f, pq0 = 0.f, ps1 = 0.f, pq1 = 0.f;
        #pragma unroll
        for (int j = 0; j < 8; ++j) {
            int c = wn * 64 + j * 8 + tig * 2;
            float2 bb = *(const float2*)(bias + c);
            acc[i][j][0] += bb.x; acc[i][j][1] += bb.y;
            acc[i][j][2] += bb.x; acc[i][j][3] += bb.y;
            ps0 += acc[i][j][0] + acc[i][j][1];
            pq0 += acc[i][j][0] * acc[i][j][0] + acc[i][j][1] * acc[i][j][1];
            ps1 += acc[i][j][2] + acc[i][j][3];
            pq1 += acc[i][j][2] * acc[i][j][2] + acc[i][j][3] * acc[i][j][3];
        }
        #pragma unroll
        for (int o = 1; o < 4; o <<= 1) {
            ps0 += __shfl_xor_sync(0xffffffffu, ps0, o);
            pq0 += __shfl_xor_sync(0xffffffffu, pq0, o);
            ps1 += __shfl_xor_sync(0xffffffffu, ps1, o);
            pq1 += __shfl_xor_sync(0xffffffffu, pq1, o);
        }
        if (tig == 0) {
            int ra = wm * 32 + i * 16 + gid;
            ssum[ra][wn] = ps0; ssq[ra][wn] = pq0;
            ssum[ra + 8][wn] = ps1; ssq[ra + 8][wn] = pq1;
        }
    }
    __syncthreads();
    #pragma unroll
    for (int i = 0; i < 2; ++i) {
        int ra = wm * 32 + i * 16 + gid;
        #pragma unroll
        for (int h = 0; h < 2; ++h) {
            int row = ra + h * 8;
            float s = ssum[row][0] + ssum[row][1];
            float q2 = ssq[row][0] + ssq[row][1];
            float m = s * (1.f / 128.f);
            float var = q2 * (1.f / 128.f) - m * m;
            float inv = rsqrtf(var + 1e-3f);
            size_t off = (EPI == 4) ? scatter_off(bm + row) : (size_t)(bm + row) * 128;
            #pragma unroll
            for (int j = 0; j < 8; ++j) {
                int c = wn * 64 + j * 8 + tig * 2;
                float2 gg = *(const float2*)(lng + c);
                float2 be = *(const float2*)(lnb + c);
                float2 xr = *(const float2*)(resid + off + c);
                float e0 = acc[i][j][2 * h], e1 = acc[i][j][2 * h + 1];
                float2 o2;
                o2.x = xr.x + (e0 - m) * inv * gg.x + be.x;
                o2.y = xr.y + (e1 - m) * inv * gg.y + be.y;
                *(float2*)(out + off + c) = o2;
            }
        }
    }
}

// ---------------- K-core: per-(window, head) attention ----------------
// R15 structure; g_o stores tf32-rounded bits (bit-identical to proj's cvt).
#define HQS 36

__global__ void __launch_bounds__(128) k_core(const float* __restrict__ mask) {
    __shared__ float q[NTOK * HQS];
    __shared__ float kk[NTOK * HQS];
    __shared__ float v[NTOK * 32];
    __shared__ float at[NTOK * NTOK];
    __shared__ int pix[NTOK];

    int t = threadIdx.x;
    int lane = t & 31, warp = t >> 5;
    int win = blockIdx.x, h = blockIdx.y;
    int b = win >> 6, wloc = win & 63, wr = wloc >> 3, wc = wloc & 7;

    if (t < NTOK) {
        int i = t / WS, j = t % WS;
        int sr = (wr * WS + i + 3) % HW;
        int sc = (wc * WS + j + 3) % HW;
        pix[t] = (b * HW + sr) * HW + sc;
    }
    __syncthreads();

    for (int idx = t; idx < NTOK * 8; idx += 128) {
        int p = idx >> 3, c4 = idx & 7;
        const float* base = g_qkv + (size_t)pix[p] * 384 + h * 32 + c4 * 4;
        *(float4*)(q + p * HQS + c4 * 4)  = *(const float4*)(base);
        *(float4*)(kk + p * HQS + c4 * 4) = *(const float4*)(base + 128);
        *(float4*)(v + p * 32 + c4 * 4)   = *(const float4*)(base + 256);
    }
    __syncthreads();

    if (t < 2 * NTOK) {
        float4* b4 = (float4*)((t < NTOK) ? (q + t * HQS) : (kk + (t - NTOK) * HQS));
        float s = 0.f;
        #pragma unroll
        for (int d = 0; d < 8; ++d) {
            float4 vv = b4[d];
            s += vv.x * vv.x + vv.y * vv.y + vv.z * vv.z + vv.w * vv.w;
        }
        float inv = rsqrtf(fmaxf(s, 1e-12f));
        #pragma unroll
        for (int d = 0; d < 8; ++d) {
            float4 vv = b4[d];
            vv.x *= inv; vv.y *= inv; vv.z *= inv; vv.w *= inv;
            b4[d] = vv;
        }
    }
    __syncthreads();

    float scal = g_scale[h];
    const float* mw = mask + (size_t)wloc * (NTOK * NTOK);
    for (int idx = t; idx < 625; idx += 128) {
        int tp = idx / 25, tq = idx - tp * 25;
        int p0 = tp * 2, q0 = tq * 2;
        int p1 = (p0 + 1 < NTOK) ? p0 + 1 : p0;
        int q1 = (q0 + 1 < NTOK) ? q0 + 1 : q0;
        const float4* qa = (const float4*)(q + p0 * HQS);
        const float4* qb = (const float4*)(q + p1 * HQS);
        const float4* ka = (const float4*)(kk + q0 * HQS);
        const float4* kb = (const float4*)(kk + q1 * HQS);
        float2 c00 = make_float2(0.f, 0.f), c01 = make_float2(0.f, 0.f);
        float2 c10 = make_float2(0.f, 0.f), c11 = make_float2(0.f, 0.f);
        #pragma unroll
        for (int d = 0; d < 8; ++d) {
            float4 qv0 = qa[d], qv1 = qb[d], kv0 = ka[d], kv1 = kb[d];
            float2 q0l = make_float2(qv0.x, qv0.y), q0h = make_float2(qv0.z, qv0.w);
            float2 q1l = make_float2(qv1.x, qv1.y), q1h = make_float2(qv1.z, qv1.w);
            float2 k0l = make_float2(kv0.x, kv0.y), k0h = make_float2(kv0.z, kv0.w);
            float2 k1l = make_float2(kv1.x, kv1.y), k1h = make_float2(kv1.z, kv1.w);
            c00 = ffma2(q0l, k0l, c00); c00 = ffma2(q0h, k0h, c00);
            c01 = ffma2(q0l, k1l, c01); c01 = ffma2(q0h, k1h, c01);
            c10 = ffma2(q1l, k0l, c10); c10 = ffma2(q1h, k0h, c10);
            c11 = ffma2(q1l, k1l, c11); c11 = ffma2(q1h, k1h, c11);
        }
        int py0 = p0 / WS, px0 = p0 - py0 * WS;
        int py1 = p1 / WS, px1 = p1 - py1 * WS;
        int qy0 = q0 / WS, qx0 = q0 - qy0 * WS;
        int qy1 = q1 / WS, qx1 = q1 - qy1 * WS;
        at[p0 * NTOK + q0] = fmaf(c00.x + c00.y, scal,
            g_bias16[((py0 - qy0 + 6) * 13 + px0 - qx0 + 6) * 4 + h] + mw[p0 * NTOK + q0]);
        if (q1 != q0)
            at[p0 * NTOK + q1] = fmaf(c01.x + c01.y, scal,
                g_bias16[((py0 - qy1 + 6) * 13 + px0 - qx1 + 6) * 4 + h] + mw[p0 * NTOK + q1]);
        if (p1 != p0) {
            at[p1 * NTOK + q0] = fmaf(c10.x + c10.y, scal,
                g_bias16[((py1 - qy0 + 6) * 13 + px1 - qx0 + 6) * 4 + h] + mw[p1 * NTOK + q0]);
            if (q1 != q0)
                at[p1 * NTOK + q1] = fmaf(c11.x + c11.y, scal,
                    g_bias16[((py1 - qy1 + 6) * 13 + px1 - qx1 + 6) * 4 + h] + mw[p1 * NTOK + q1]);
        }
    }
    __syncthreads();

    for (int row = warp; row < NTOK; row += 4) {
        float* r = at + row * NTOK;
        float v0 = r[lane < NTOK ? lane : 0];
        if (lane >= NTOK) v0 = -1e30f;
        float v1 = (lane + 32 < NTOK) ? r[lane + 32] : -1e30f;
        float m = fmaxf(v0, v1);
        #pragma unroll
        for (int o = 16; o; o >>= 1) m = fmaxf(m, __shfl_xor_sync(0xffffffffu, m, o));
        float e0 = (lane < NTOK) ? expf(v0 - m) : 0.f;
        float e1 = (lane + 32 < NTOK) ? expf(v1 - m) : 0.f;
        float s = e0 + e1;
        #pragma unroll
        for (int o = 16; o; o >>= 1) s += __shfl_xor_sync(0xffffffffu, s, o);
        float inv = 1.f / s;
        if (lane < NTOK) r[lane] = e0 * inv;
        if (lane + 32 < NTOK) r[lane + 32] = e1 * inv;
    }
    __syncthreads();

    const float2* v2 = (const float2*)v;
    for (int idx = t; idx < 400; idx += 128) {
        int pp = idx >> 4, cp = idx & 15;
        int p0 = pp * 2, p1 = p0 + 1;
        bool has1 = (p1 < NTOK);
        const float* ar0 = at + p0 * NTOK;
        const float* ar1 = at + (has1 ? p1 : p0) * NTOK;
        float2 acc0 = make_float2(0.f, 0.f), acc1 = make_float2(0.f, 0.f);
        #pragma unroll 7
        for (int qq = 0; qq < NTOK; ++qq) {
            float2 vv = v2[qq * 16 + cp];
            float a0 = ar0[qq], a1 = ar1[qq];
            acc0 = ffma2(make_float2(a0, a0), vv, acc0);
            acc1 = ffma2(make_float2(a1, a1), vv, acc1);
        }
        acc0.x = tf32r(acc0.x); acc0.y = tf32r(acc0.y);
        acc1.x = tf32r(acc1.x); acc1.y = tf32r(acc1.y);
        *(float2*)(g_o + ((size_t)win * NTOK + p0) * 128 + h * 32 + cp * 2) = acc0;
        if (has1)
            *(float2*)(g_o + ((size_t)win * NTOK + p1) * 128 + h * 32 + cp * 2) = acc1;
    }
}

// ---------------- launch ----------------
extern "C" void kernel_launch(void* const* d_in, const int* in_sizes, int n_in,
                              void* d_out, int out_size) {
    const float* x           = (const float*)d_in[0];
    const float* mask        = (const float*)d_in[1];
    const float* norm1_g     = (const float*)d_in[2];
    const float* norm1_b     = (const float*)d_in[3];
    const float* qkv_w       = (const float*)d_in[4];
    const float* q_bias      = (const float*)d_in[5];
    const float* v_bias      = (const float*)d_in[6];
    const float* logit_scale = (const float*)d_in[7];
    const float* rpe_w1      = (const float*)d_in[8];
    const float* rpe_b1      = (const float*)d_in[9];
    const float* rpe_w2      = (const float*)d_in[10];
    const float* proj_w      = (const float*)d_in[11];
    const float* proj_b      = (const float*)d_in[12];
    const float* norm2_g     = (const float*)d_in[13];
    const float* norm2_b     = (const float*)d_in[14];
    const float* fc1_w       = (const float*)d_in[15];
    const float* fc1_b       = (const float*)d_in[16];
    const float* fc2_w       = (const float*)d_in[17];
    const float* fc2_b       = (const float*)d_in[18];
    float* out = (float*)d_out;

    float *p_qkv, *p_o, *p_x1, *p_h, *p_qb;
    float *p_wqkv, *p_wproj, *p_wfc1, *p_wfc2;
    cudaGetSymbolAddress((void**)&p_qkv, g_qkv);
    cudaGetSymbolAddress((void**)&p_o,   g_o);
    cudaGetSymbolAddress((void**)&p_x1,  g_x1);
    cudaGetSymbolAddress((void**)&p_h,   g_h);
    cudaGetSymbolAddress((void**)&p_qb,  g_qkvbias);
    cudaGetSymbolAddress((void**)&p_wqkv,  g_wqkv);
    cudaGetSymbolAddress((void**)&p_wproj, g_wproj);
    cudaGetSymbolAddress((void**)&p_wfc1,  g_wfc1);
    cudaGetSymbolAddress((void**)&p_wfc2,  g_wfc2);

    cudaFuncSetAttribute(k_gemm_ares<384, 0>, cudaFuncAttributeMaxDynamicSharedMemorySize, SM_ARES);
    cudaFuncSetAttribute(k_gemm_ares<512, 2>, cudaFuncAttributeMaxDynamicSharedMemorySize, SM_ARES);

    k_round<<<(128 * 384 + 255) / 256, 256>>>(qkv_w,  p_wqkv,  128 * 384);
    k_round<<<(128 * 128 + 255) / 256, 256>>>(proj_w, p_wproj, 128 * 128);
    k_round<<<(128 * 512 + 255) / 256, 256>>>(fc1_w,  p_wfc1,  128 * 512);
    k_round<<<(512 * 128 + 255) / 256, 256>>>(fc2_w,  p_wfc2,  512 * 128);
    k_prep<<<170, 128>>>(logit_scale, rpe_w1, rpe_b1, rpe_w2, q_bias, v_bias);

    k_gemm_ares<384, 0><<<NPIX / 128, 256, SM_ARES>>>(x, p_wqkv, p_qb, p_qkv);

    dim3 gc(NWIN_TOT, 4);
    k_core<<<gc, 128>>>(mask);

    dim3 gp(NPIX / 128, 1);
    k_gemm_tc<128, 128, 4><<<gp, 256>>>(p_o, p_wproj, proj_b, p_x1,
                                        x, norm1_g, norm1_b);

    k_gemm_ares<512, 2><<<NPIX / 128, 256, SM_ARES>>>(p_x1, p_wfc1, fc1_b, p_h);

    dim3 g2(NPIX / 128, 1);
    k_gemm_tc<512, 128, 3><<<g2, 256>>>(p_h, p_wfc2, fc2_b, out,
                                        p_x1, norm2_g, norm2_b);
}

// round 17
// speedup vs baseline: 1.1506x; 1.0075x over previous
#include <cuda_runtime.h>
#include <math.h>

#define HW 56
#define CDIM 128
#define WS 7
#define NTOK 49
#define NWIN_TOT 4096
#define NPIX 200704           // 64*56*56

typedef unsigned long long u64_t;

// ---------------- device scratch ----------------
__device__ float g_qkv[(size_t)NPIX * 384];      // q,k cosine-normalized
__device__ float g_o[(size_t)NPIX * 128];        // tf32-rounded bits
__device__ float g_x1[(size_t)NPIX * 128];       // full fp32 (residual source)
__device__ float g_h[(size_t)NPIX * 512];        // tf32-rounded bits
__device__ float g_bias16[13 * 13 * 4];
__device__ float g_scale[4];
__device__ float g_qkvbias[384];
// tf32-rounded weight copies
__device__ float g_wqkv[128 * 384];
__device__ float g_wproj[128 * 128];
__device__ float g_wfc1[128 * 512];
__device__ float g_wfc2[512 * 128];

// ---------------- helpers ----------------
__device__ __forceinline__ float2 ffma2(float2 a, float2 b, float2 c) {
    u64_t au = *reinterpret_cast<u64_t*>(&a);
    u64_t bu = *reinterpret_cast<u64_t*>(&b);
    u64_t cu = *reinterpret_cast<u64_t*>(&c);
    u64_t du;
    asm("fma.rn.f32x2 %0, %1, %2, %3;" : "=l"(du) : "l"(au), "l"(bu), "l"(cu));
    return *reinterpret_cast<float2*>(&du);
}

__device__ __forceinline__ void cp_async16(void* smem_dst, const void* gmem_src) {
    unsigned sa = (unsigned)__cvta_generic_to_shared(smem_dst);
    asm volatile("cp.async.cg.shared.global [%0], [%1], 16;" :: "r"(sa), "l"(gmem_src));
}
__device__ __forceinline__ void cp_async_commit() {
    asm volatile("cp.async.commit_group;");
}
__device__ __forceinline__ void cp_async_wait_all() {
    asm volatile("cp.async.wait_group 0;");
}

__device__ __forceinline__ unsigned tf32_of(float f) {
    unsigned u;
    asm("cvt.rna.tf32.f32 %0, %1;" : "=r"(u) : "f"(f));
    return u;
}
__device__ __forceinline__ float tf32r(float f) {
    return __uint_as_float(tf32_of(f));
}

__device__ __forceinline__ void mma_tf32(float d[4], const unsigned a[4],
                                         const unsigned b[2], const float c[4]) {
    asm("mma.sync.aligned.m16n8k8.row.col.f32.tf32.tf32.f32 "
        "{%0,%1,%2,%3}, {%4,%5,%6,%7}, {%8,%9}, {%10,%11,%12,%13};"
        : "=f"(d[0]), "=f"(d[1]), "=f"(d[2]), "=f"(d[3])
        : "r"(a[0]), "r"(a[1]), "r"(a[2]), "r"(a[3]),
          "r"(b[0]), "r"(b[1]),
          "f"(c[0]), "f"(c[1]), "f"(c[2]), "f"(c[3]));
}

__device__ __forceinline__ float gelu_exact(float z) {
    return 0.5f * z * (1.0f + erff(z * 0.7071067811865475f));
}

__device__ __forceinline__ size_t scatter_off(int r) {
    unsigned r_ = (unsigned)r;
    unsigned win = r_ / 49u, p = r_ - win * 49u;
    unsigned b = win >> 6, wloc = win & 63u, wr = wloc >> 3, wc = wloc & 7u;
    unsigned ii = p / 7u, jj = p - ii * 7u;
    unsigned sr = wr * 7 + ii + 3; if (sr >= 56) sr -= 56;
    unsigned sc = wc * 7 + jj + 3; if (sc >= 56) sc -= 56;
    return ((size_t)((b * 56 + sr) * 56 + sc)) * 128;
}

__device__ __forceinline__ float quad_sum(float s) {
    s += __shfl_xor_sync(0xffffffffu, s, 1);
    s += __shfl_xor_sync(0xffffffffu, s, 2);
    return s;
}

// ---------------- K0: round weights to tf32 bits ----------------
__global__ void k_round(const float* __restrict__ src, float* __restrict__ dst, int n) {
    int i = blockIdx.x * 256 + threadIdx.x;
    if (i < n) dst[i] = tf32r(src[i]);
}

// ---------------- K1: prep ----------------
__device__ __forceinline__ float rpb_f(float v) {
    float sv = v * (2.0f / 9.0f);
    float s = (sv > 0.f) ? 1.f : ((sv < 0.f) ? -1.f : 0.f);
    return s * log1pf(fabsf(sv)) * (1.0f / 2.0794415416798357f);
}

__global__ void k_prep(const float* __restrict__ logit_scale,
                       const float* __restrict__ rpe_w1,
                       const float* __restrict__ rpe_b1,
                       const float* __restrict__ rpe_w2,
                       const float* __restrict__ q_bias,
                       const float* __restrict__ v_bias) {
    int bid = blockIdx.x, t = threadIdx.x;
    if (bid == 169) {
        if (t < 4) g_scale[t] = expf(fminf(logit_scale[t], logf(100.0f)));
        for (int c = t; c < 384; c += 128)
            g_qkvbias[c] = (c < 128) ? q_bias[c] : (c >= 256 ? v_bias[c - 256] : 0.f);
        return;
    }
    int dy = bid / 13 - 6, dx = bid % 13 - 6;
    float t0 = rpb_f((float)dy), t1 = rpb_f((float)dx);
    float a0 = 0, a1 = 0, a2 = 0, a3 = 0;
    for (int k = t; k < 512; k += 128) {
        float hsum = fmaf(t0, rpe_w1[k], fmaf(t1, rpe_w1[512 + k], rpe_b1[k]));
        if (hsum > 0.f) {
            const float* w2r = rpe_w2 + k * 4;
            a0 = fmaf(hsum, w2r[0], a0);
            a1 = fmaf(hsum, w2r[1], a1);
            a2 = fmaf(hsum, w2r[2], a2);
            a3 = fmaf(hsum, w2r[3], a3);
        }
    }
    #pragma unroll
    for (int o = 16; o; o >>= 1) {
        a0 += __shfl_xor_sync(0xffffffffu, a0, o);
        a1 += __shfl_xor_sync(0xffffffffu, a1, o);
        a2 += __shfl_xor_sync(0xffffffffu, a2, o);
        a3 += __shfl_xor_sync(0xffffffffu, a3, o);
    }
    __shared__ float red[4][4];
    int w = t >> 5;
    if ((t & 31) == 0) { red[w][0] = a0; red[w][1] = a1; red[w][2] = a2; red[w][3] = a3; }
    __syncthreads();
    if (t < 4) {
        float s = red[0][t] + red[1][t] + red[2][t] + red[3][t];
        g_bias16[bid * 4 + t] = 16.f / (1.f + expf(-s));
    }
}

// =================================================================
// A-resident tf32 GEMM (K=128, N>128): qkv / fc1
// EPI: 2 = bias + gelu + tf32-round (fc1)
//      5 = qkv: bias + cosine-normalize q,k heads (nt 0,1)
// =================================================================
#define ARS 132
#define BRS 136
#define SM_ARES (128*ARS*4 + 2*16*BRS*4)

template<int N, int EPI>
__global__ void __launch_bounds__(256, 2) k_gemm_ares(
    const float* __restrict__ A, const float* __restrict__ Bm,
    const float* __restrict__ bias, float* __restrict__ out)
{
    extern __shared__ float smdyn[];
    float* Asm = smdyn;
    float* Bs0 = Asm + 128 * ARS;
    float* Bs1 = Bs0 + 16 * BRS;

    int t = threadIdx.x;
    int lane = t & 31, warp = t >> 5;
    int wm = warp >> 1, wn = warp & 1;
    int gid = lane >> 2, tig = lane & 3;
    int bm = blockIdx.x * 128;

    int bk = t >> 4, bc = (t & 15) * 8;

    {
        const float* Ap = A + (size_t)(bm + (t >> 1)) * 128 + (t & 1) * 64;
        float* as = Asm + (t >> 1) * ARS + (t & 1) * 64;
        #pragma unroll
        for (int j = 0; j < 16; ++j) cp_async16(as + j * 4, Ap + j * 4);
        cp_async_commit();
    }
    {
        const float* Bp = Bm + (size_t)bk * N + bc;
        cp_async16(Bs0 + bk * BRS + bc, Bp);
        cp_async16(Bs0 + bk * BRS + bc + 4, Bp + 4);
        cp_async_commit();
    }
    cp_async_wait_all();
    {
        float* as = Asm + (t >> 1) * ARS + (t & 1) * 64;
        #pragma unroll 8
        for (int i = 0; i < 64; ++i) as[i] = tf32r(as[i]);
    }
    __syncthreads();

    float acc[2][8][4];
    #pragma unroll
    for (int i = 0; i < 2; ++i)
        #pragma unroll
        for (int j = 0; j < 8; ++j)
            #pragma unroll
            for (int e = 0; e < 4; ++e) acc[i][j][e] = 0.f;

    const int T = (N / 128) * 8;
    #pragma unroll 1
    for (int st = 0; st < T; ++st) {
        float* bsC = (st & 1) ? Bs1 : Bs0;
        float* bsN = (st & 1) ? Bs0 : Bs1;
        if (st + 1 < T) {
            int nt1 = (st + 1) >> 3, s1 = (st + 1) & 7;
            const float* Bp = Bm + (size_t)(s1 * 16 + bk) * N + nt1 * 128 + bc;
            cp_async16(bsN + bk * BRS + bc, Bp);
            cp_async16(bsN + bk * BRS + bc + 4, Bp + 4);
            cp_async_commit();
        }
        int kb0 = (st & 7) * 16;
        #pragma unroll
        for (int kb = 0; kb < 16; kb += 8) {
            unsigned af[2][4];
            #pragma unroll
            for (int i = 0; i < 2; ++i) {
                const float* ab = &Asm[(wm * 32 + i * 16 + gid) * ARS + kb0 + kb + tig];
                af[i][0] = __float_as_uint(ab[0]);
                af[i][1] = __float_as_uint(ab[8 * ARS]);
                af[i][2] = __float_as_uint(ab[4]);
                af[i][3] = __float_as_uint(ab[8 * ARS + 4]);
            }
            #pragma unroll
            for (int j = 0; j < 8; ++j) {
                unsigned bf[2];
                int ncol = wn * 64 + j * 8 + gid;
                bf[0] = __float_as_uint(bsC[(kb + tig) * BRS + ncol]);
                bf[1] = __float_as_uint(bsC[(kb + tig + 4) * BRS + ncol]);
                mma_tf32(acc[0][j], af[0], bf, acc[0][j]);
                mma_tf32(acc[1][j], af[1], bf, acc[1][j]);
            }
        }

        if ((st & 7) == 7) {
            int nt = st >> 3;
            int cb = nt * 128 + wn * 64;
            #pragma unroll
            for (int i = 0; i < 2; ++i) {
                int rr0 = bm + wm * 32 + i * 16 + gid;
                float2 vv0[8], vv1[8];
                #pragma unroll
                for (int j = 0; j < 8; ++j) {
                    int c = cb + j * 8 + tig * 2;
                    float2 bb = *(const float2*)(bias + c);
                    vv0[j] = make_float2(acc[i][j][0] + bb.x, acc[i][j][1] + bb.y);
                    vv1[j] = make_float2(acc[i][j][2] + bb.x, acc[i][j][3] + bb.y);
                }
                if (EPI == 5 && nt < 2) {
                    // cosine-normalize per head (head A: j0-3, head B: j4-7)
                    float sA0 = 0.f, sA1 = 0.f, sB0 = 0.f, sB1 = 0.f;
                    #pragma unroll
                    for (int j = 0; j < 4; ++j) {
                        sA0 += vv0[j].x * vv0[j].x + vv0[j].y * vv0[j].y;
                        sA1 += vv1[j].x * vv1[j].x + vv1[j].y * vv1[j].y;
                        sB0 += vv0[j + 4].x * vv0[j + 4].x + vv0[j + 4].y * vv0[j + 4].y;
                        sB1 += vv1[j + 4].x * vv1[j + 4].x + vv1[j + 4].y * vv1[j + 4].y;
                    }
                    sA0 = quad_sum(sA0); sA1 = quad_sum(sA1);
                    sB0 = quad_sum(sB0); sB1 = quad_sum(sB1);
                    float iA0 = rsqrtf(fmaxf(sA0, 1e-12f));
                    float iA1 = rsqrtf(fmaxf(sA1, 1e-12f));
                    float iB0 = rsqrtf(fmaxf(sB0, 1e-12f));
                    float iB1 = rsqrtf(fmaxf(sB1, 1e-12f));
                    #pragma unroll
                    for (int j = 0; j < 4; ++j) {
                        vv0[j].x *= iA0; vv0[j].y *= iA0;
                        vv1[j].x *= iA1; vv1[j].y *= iA1;
                        vv0[j + 4].x *= iB0; vv0[j + 4].y *= iB0;
                        vv1[j + 4].x *= iB1; vv1[j + 4].y *= iB1;
                    }
                }
                #pragma unroll
                for (int j = 0; j < 8; ++j) {
                    int c = cb + j * 8 + tig * 2;
                    float2 v0 = vv0[j], v1 = vv1[j];
                    if (EPI == 2) {
                        v0.x = tf32r(gelu_exact(v0.x)); v0.y = tf32r(gelu_exact(v0.y));
                        v1.x = tf32r(gelu_exact(v1.x)); v1.y = tf32r(gelu_exact(v1.y));
                    }
                    *(float2*)(out + (size_t)rr0 * N + c) = v0;
                    *(float2*)(out + (size_t)(rr0 + 8) * N + c) = v1;
                }
            }
            if (st + 1 < T) {
                #pragma unroll
                for (int i = 0; i < 2; ++i)
                    #pragma unroll
                    for (int j = 0; j < 8; ++j)
                        #pragma unroll
                        for (int e = 0; e < 4; ++e) acc[i][j][e] = 0.f;
            }
        }
        if (st + 1 < T) {
            cp_async_wait_all();
            __syncthreads();
        }
    }
}

// =================================================================
// streaming tf32 GEMM: BM=128, BN=128, 2-stage cp.async, zero in-loop cvt.
// EPI 3 = bias+LN+residual (row order) ; 4 = bias+LN+residual (scatter)
// =================================================================
#define AS 20
#define BSo 136

template<int K, int N, int EPI>
__global__ void __launch_bounds__(256, 2) k_gemm_tc(
    const float* __restrict__ A, const float* __restrict__ Bm,
    const float* __restrict__ bias, float* __restrict__ out,
    const float* __restrict__ resid, const float* __restrict__ lng,
    const float* __restrict__ lnb)
{
    __shared__ __align__(16) float Asm[2][128 * AS];
    __shared__ __align__(16) float Bs[2][16 * BSo];
    __shared__ float ssum[128][2], ssq[128][2];
    int t = threadIdx.x;
    int lane = t & 31, warp = t >> 5;
    int wm = warp >> 1, wn = warp & 1;
    int gid = lane >> 2, tig = lane & 3;
    int bm = blockIdx.x * 128, bn = blockIdx.y * 128;

    int ar0 = t >> 1, ac0 = (t & 1) * 8;
    int bk = t >> 4, bc = (t & 15) * 8;

    const float* Ap = A + (size_t)(bm + ar0) * K + ac0;
    const float* Bp = Bm + (size_t)bk * N + bn + bc;

    cp_async16(&Asm[0][ar0 * AS + ac0], Ap);
    cp_async16(&Asm[0][ar0 * AS + ac0 + 4], Ap + 4);
    cp_async16(&Bs[0][bk * BSo + bc], Bp);
    cp_async16(&Bs[0][bk * BSo + bc + 4], Bp + 4);
    cp_async_commit();
    cp_async_wait_all();
    __syncthreads();

    float acc[2][8][4];
    #pragma unroll
    for (int i = 0; i < 2; ++i)
        #pragma unroll
        for (int j = 0; j < 8; ++j)
            #pragma unroll
            for (int e = 0; e < 4; ++e) acc[i][j][e] = 0.f;

    const int S = K / 16;
    #pragma unroll 1
    for (int s = 0; s < S; ++s) {
        int buf = s & 1;
        if (s + 1 < S) {
            int nb = buf ^ 1;
            const float* a0 = Ap + (s + 1) * 16;
            const float* b0 = Bp + (size_t)(s + 1) * 16 * N;
            cp_async16(&Asm[nb][ar0 * AS + ac0], a0);
            cp_async16(&Asm[nb][ar0 * AS + ac0 + 4], a0 + 4);
            cp_async16(&Bs[nb][bk * BSo + bc], b0);
            cp_async16(&Bs[nb][bk * BSo + bc + 4], b0 + 4);
            cp_async_commit();
        }
        #pragma unroll
        for (int kb = 0; kb < 16; kb += 8) {
            unsigned af[2][4];
            #pragma unroll
            for (int i = 0; i < 2; ++i) {
                const float* ab = &Asm[buf][(wm * 32 + i * 16 + gid) * AS + kb + tig];
                af[i][0] = __float_as_uint(ab[0]);
                af[i][1] = __float_as_uint(ab[8 * AS]);
                af[i][2] = __float_as_uint(ab[4]);
                af[i][3] = __float_as_uint(ab[8 * AS + 4]);
            }
            #pragma unroll
            for (int j = 0; j < 8; ++j) {
                unsigned bf[2];
                int ncol = wn * 64 + j * 8 + gid;
                bf[0] = __float_as_uint(Bs[buf][(kb + tig) * BSo + ncol]);
                bf[1] = __float_as_uint(Bs[buf][(kb + tig + 4) * BSo + ncol]);
                mma_tf32(acc[0][j], af[0], bf, acc[0][j]);
                mma_tf32(acc[1][j], af[1], bf, acc[1][j]);
            }
        }
        if (s + 1 < S) {
            cp_async_wait_all();
            __syncthreads();
        }
    }

    __syncthreads();
    #pragma unroll
    for (int i = 0; i < 2; ++i) {
        float ps0 = 0.f, pq0 = 0.f, ps1 = 0.f, pq1 = 0.f;
        #pragma unroll
        for (int j = 0; j < 8; ++j) {
            int c = wn * 64 + j * 8 + tig * 2;
            float2 bb = *(const float2*)(bias + c);
            acc[i][j][0] += bb.x; acc[i][j][1] += bb.y;
            acc[i][j][2] += bb.x; acc[i][j][3] += bb.y;
            ps0 += acc[i][j][0] + acc[i][j][1];
            pq0 += acc[i][j][0] * acc[i][j][0] + acc[i][j][1] * acc[i][j][1];
            ps1 += acc[i][j][2] + acc[i][j][3];
            pq1 += acc[i][j][2] * acc[i][j][2] + acc[i][j][3] * acc[i][j][3];
        }
        #pragma unroll
        for (int o = 1; o < 4; o <<= 1) {
            ps0 += __shfl_xor_sync(0xffffffffu, ps0, o);
            pq0 += __shfl_xor_sync(0xffffffffu, pq0, o);
            ps1 += __shfl_xor_sync(0xffffffffu, ps1, o);
            pq1 += __shfl_xor_sync(0xffffffffu, pq1, o);
        }
        if (tig == 0) {
            int ra = wm * 32 + i * 16 + gid;
            ssum[ra][wn] = ps0; ssq[ra][wn] = pq0;
            ssum[ra + 8][wn] = ps1; ssq[ra + 8][wn] = pq1;
        }
    }
    __syncthreads();
    #pragma unroll
    for (int i = 0; i < 2; ++i) {
        int ra = wm * 32 + i * 16 + gid;
        #pragma unroll
        for (int h = 0; h < 2; ++h) {
            int row = ra + h * 8;
            float s = ssum[row][0] + ssum[row][1];
            float q2 = ssq[row][0] + ssq[row][1];
            float m = s * (1.f / 128.f);
            float var = q2 * (1.f / 128.f) - m * m;
            float inv = rsqrtf(var + 1e-3f);
            size_t off = (EPI == 4) ? scatter_off(bm + row) : (size_t)(bm + row) * 128;
            #pragma unroll
            for (int j = 0; j < 8; ++j) {
                int c = wn * 64 + j * 8 + tig * 2;
                float2 gg = *(const float2*)(lng + c);
                float2 be = *(const float2*)(lnb + c);
                float2 xr = *(const float2*)(resid + off + c);
                float e0 = acc[i][j][2 * h], e1 = acc[i][j][2 * h + 1];
                float2 o2;
                o2.x = xr.x + (e0 - m) * inv * gg.x + be.x;
                o2.y = xr.y + (e1 - m) * inv * gg.y + be.y;
                *(float2*)(out + off + c) = o2;
            }
        }
    }
}

// ---------------- K-core: per-(window, head) attention ----------------
// q/k arrive pre-normalized; normalize phase removed.
#define HQS 36

__global__ void __launch_bounds__(128) k_core(const float* __restrict__ mask) {
    __shared__ float q[NTOK * HQS];
    __shared__ float kk[NTOK * HQS];
    __shared__ float v[NTOK * 32];
    __shared__ float at[NTOK * NTOK];
    __shared__ int pix[NTOK];

    int t = threadIdx.x;
    int lane = t & 31, warp = t >> 5;
    int win = blockIdx.x, h = blockIdx.y;
    int b = win >> 6, wloc = win & 63, wr = wloc >> 3, wc = wloc & 7;

    if (t < NTOK) {
        int i = t / WS, j = t % WS;
        int sr = (wr * WS + i + 3) % HW;
        int sc = (wc * WS + j + 3) % HW;
        pix[t] = (b * HW + sr) * HW + sc;
    }
    __syncthreads();

    for (int idx = t; idx < NTOK * 8; idx += 128) {
        int p = idx >> 3, c4 = idx & 7;
        const float* base = g_qkv + (size_t)pix[p] * 384 + h * 32 + c4 * 4;
        *(float4*)(q + p * HQS + c4 * 4)  = *(const float4*)(base);
        *(float4*)(kk + p * HQS + c4 * 4) = *(const float4*)(base + 128);
        *(float4*)(v + p * 32 + c4 * 4)   = *(const float4*)(base + 256);
    }
    __syncthreads();

    float scal = g_scale[h];
    const float* mw = mask + (size_t)wloc * (NTOK * NTOK);
    for (int idx = t; idx < 625; idx += 128) {
        int tp = idx / 25, tq = idx - tp * 25;
        int p0 = tp * 2, q0 = tq * 2;
        int p1 = (p0 + 1 < NTOK) ? p0 + 1 : p0;
        int q1 = (q0 + 1 < NTOK) ? q0 + 1 : q0;
        const float4* qa = (const float4*)(q + p0 * HQS);
        const float4* qb = (const float4*)(q + p1 * HQS);
        const float4* ka = (const float4*)(kk + q0 * HQS);
        const float4* kb = (const float4*)(kk + q1 * HQS);
        float2 c00 = make_float2(0.f, 0.f), c01 = make_float2(0.f, 0.f);
        float2 c10 = make_float2(0.f, 0.f), c11 = make_float2(0.f, 0.f);
        #pragma unroll
        for (int d = 0; d < 8; ++d) {
            float4 qv0 = qa[d], qv1 = qb[d], kv0 = ka[d], kv1 = kb[d];
            float2 q0l = make_float2(qv0.x, qv0.y), q0h = make_float2(qv0.z, qv0.w);
            float2 q1l = make_float2(qv1.x, qv1.y), q1h = make_float2(qv1.z, qv1.w);
            float2 k0l = make_float2(kv0.x, kv0.y), k0h = make_float2(kv0.z, kv0.w);
            float2 k1l = make_float2(kv1.x, kv1.y), k1h = make_float2(kv1.z, kv1.w);
            c00 = ffma2(q0l, k0l, c00); c00 = ffma2(q0h, k0h, c00);
            c01 = ffma2(q0l, k1l, c01); c01 = ffma2(q0h, k1h, c01);
            c10 = ffma2(q1l, k0l, c10); c10 = ffma2(q1h, k0h, c10);
            c11 = ffma2(q1l, k1l, c11); c11 = ffma2(q1h, k1h, c11);
        }
        int py0 = p0 / WS, px0 = p0 - py0 * WS;
        int py1 = p1 / WS, px1 = p1 - py1 * WS;
        int qy0 = q0 / WS, qx0 = q0 - qy0 * WS;
        int qy1 = q1 / WS, qx1 = q1 - qy1 * WS;
        at[p0 * NTOK + q0] = fmaf(c00.x + c00.y, scal,
            g_bias16[((py0 - qy0 + 6) * 13 + px0 - qx0 + 6) * 4 + h] + mw[p0 * NTOK + q0]);
        if (q1 != q0)
            at[p0 * NTOK + q1] = fmaf(c01.x + c01.y, scal,
                g_bias16[((py0 - qy1 + 6) * 13 + px0 - qx1 + 6) * 4 + h] + mw[p0 * NTOK + q1]);
        if (p1 != p0) {
            at[p1 * NTOK + q0] = fmaf(c10.x + c10.y, scal,
                g_bias16[((py1 - qy0 + 6) * 13 + px1 - qx0 + 6) * 4 + h] + mw[p1 * NTOK + q0]);
            if (q1 != q0)
                at[p1 * NTOK + q1] = fmaf(c11.x + c11.y, scal,
                    g_bias16[((py1 - qy1 + 6) * 13 + px1 - qx1 + 6) * 4 + h] + mw[p1 * NTOK + q1]);
        }
    }
    __syncthreads();

    for (int row = warp; row < NTOK; row += 4) {
        float* r = at + row * NTOK;
        float v0 = r[lane < NTOK ? lane : 0];
        if (lane >= NTOK) v0 = -1e30f;
        float v1 = (lane + 32 < NTOK) ? r[lane + 32] : -1e30f;
        float m = fmaxf(v0, v1);
        #pragma unroll
        for (int o = 16; o; o >>= 1) m = fmaxf(m, __shfl_xor_sync(0xffffffffu, m, o));
        float e0 = (lane < NTOK) ? expf(v0 - m) : 0.f;
        float e1 = (lane + 32 < NTOK) ? expf(v1 - m) : 0.f;
        float s = e0 + e1;
        #pragma unroll
        for (int o = 16; o; o >>= 1) s += __shfl_xor_sync(0xffffffffu, s, o);
        float inv = 1.f / s;
        if (lane < NTOK) r[lane] = e0 * inv;
        if (lane + 32 < NTOK) r[lane + 32] = e1 * inv;
    }
    __syncthreads();

    const float2* v2 = (const float2*)v;
    for (int idx = t; idx < 400; idx += 128) {
        int pp = idx >> 4, cp = idx & 15;
        int p0 = pp * 2, p1 = p0 + 1;
        bool has1 = (p1 < NTOK);
        const float* ar0 = at + p0 * NTOK;
        const float* ar1 = at + (has1 ? p1 : p0) * NTOK;
        float2 acc0 = make_float2(0.f, 0.f), acc1 = make_float2(0.f, 0.f);
        #pragma unroll 7
        for (int qq = 0; qq < NTOK; ++qq) {
            float2 vv = v2[qq * 16 + cp];
            float a0 = ar0[qq], a1 = ar1[qq];
            acc0 = ffma2(make_float2(a0, a0), vv, acc0);
            acc1 = ffma2(make_float2(a1, a1), vv, acc1);
        }
        acc0.x = tf32r(acc0.x); acc0.y = tf32r(acc0.y);
        acc1.x = tf32r(acc1.x); acc1.y = tf32r(acc1.y);
        *(float2*)(g_o + ((size_t)win * NTOK + p0) * 128 + h * 32 + cp * 2) = acc0;
        if (has1)
            *(float2*)(g_o + ((size_t)win * NTOK + p1) * 128 + h * 32 + cp * 2) = acc1;
    }
}

// ---------------- launch ----------------
extern "C" void kernel_launch(void* const* d_in, const int* in_sizes, int n_in,
                              void* d_out, int out_size) {
    const float* x           = (const float*)d_in[0];
    const float* mask        = (const float*)d_in[1];
    const float* norm1_g     = (const float*)d_in[2];
    const float* norm1_b     = (const float*)d_in[3];
    const float* qkv_w       = (const float*)d_in[4];
    const float* q_bias      = (const float*)d_in[5];
    const float* v_bias      = (const float*)d_in[6];
    const float* logit_scale = (const float*)d_in[7];
    const float* rpe_w1      = (const float*)d_in[8];
    const float* rpe_b1      = (const float*)d_in[9];
    const float* rpe_w2      = (const float*)d_in[10];
    const float* proj_w      = (const float*)d_in[11];
    const float* proj_b      = (const float*)d_in[12];
    const float* norm2_g     = (const float*)d_in[13];
    const float* norm2_b     = (const float*)d_in[14];
    const float* fc1_w       = (const float*)d_in[15];
    const float* fc1_b       = (const float*)d_in[16];
    const float* fc2_w       = (const float*)d_in[17];
    const float* fc2_b       = (const float*)d_in[18];
    float* out = (float*)d_out;

    float *p_qkv, *p_o, *p_x1, *p_h, *p_qb;
    float *p_wqkv, *p_wproj, *p_wfc1, *p_wfc2;
    cudaGetSymbolAddress((void**)&p_qkv, g_qkv);
    cudaGetSymbolAddress((void**)&p_o,   g_o);
    cudaGetSymbolAddress((void**)&p_x1,  g_x1);
    cudaGetSymbolAddress((void**)&p_h,   g_h);
    cudaGetSymbolAddress((void**)&p_qb,  g_qkvbias);
    cudaGetSymbolAddress((void**)&p_wqkv,  g_wqkv);
    cudaGetSymbolAddress((void**)&p_wproj, g_wproj);
    cudaGetSymbolAddress((void**)&p_wfc1,  g_wfc1);
    cudaGetSymbolAddress((void**)&p_wfc2,  g_wfc2);

    cudaFuncSetAttribute(k_gemm_ares<384, 5>, cudaFuncAttributeMaxDynamicSharedMemorySize, SM_ARES);
    cudaFuncSetAttribute(k_gemm_ares<512, 2>, cudaFuncAttributeMaxDynamicSharedMemorySize, SM_ARES);

    k_round<<<(128 * 384 + 255) / 256, 256>>>(qkv_w,  p_wqkv,  128 * 384);
    k_round<<<(128 * 128 + 255) / 256, 256>>>(proj_w, p_wproj, 128 * 128);
    k_round<<<(128 * 512 + 255) / 256, 256>>>(fc1_w,  p_wfc1,  128 * 512);
    k_round<<<(512 * 128 + 255) / 256, 256>>>(fc2_w,  p_wfc2,  512 * 128);
    k_prep<<<170, 128>>>(logit_scale, rpe_w1, rpe_b1, rpe_w2, q_bias, v_bias);

    k_gemm_ares<384, 5><<<NPIX / 128, 256, SM_ARES>>>(x, p_wqkv, p_qb, p_qkv);

    dim3 gc(NWIN_TOT, 4);
    k_core<<<gc, 128>>>(mask);

    dim3 gp(NPIX / 128, 1);
    k_gemm_tc<128, 128, 4><<<gp, 256>>>(p_o, p_wproj, proj_b, p_x1,
                                        x, norm1_g, norm1_b);

    k_gemm_ares<512, 2><<<NPIX / 128, 256, SM_ARES>>>(p_x1, p_wfc1, fc1_b, p_h);

    dim3 g2(NPIX / 128, 1);
    k_gemm_tc<512, 128, 3><<<g2, 256>>>(p_h, p_wfc2, fc2_b, out,
                                        p_x1, norm2_g, norm2_b);
}